// round 9
// baseline (speedup 1.0000x reference)
#include <cuda_runtime.h>
#include <cuda_fp16.h>
#include <math.h>
#include <stdint.h>

#define BB   2
#define TT   2048
#define DD   1024
#define HH   16
#define DHH  64
#define MT   4096            // B*T
#define D3   3072            // 3*D
#define D4   4096            // 4*D
#define D8   8192            // gate+up stacked

// ---------------- scratch (static device arrays; no allocation) ----------------
__device__ __half g_h[MT * DD];                      // rmsnorm output (f16)
__device__ __half g_qh[MT * DD];                     // q, f16, pre-scaled by 1/8
__device__ __half g_att[MT * DD];                    // attention out (f16)
__device__ __half g_t1[(size_t)MT * D4];             // silu(gate)*up (f16)
__device__ __half g_wh[16 * 1024 * 1024];            // converted weights (f16)
__device__ __half g_kt[(size_t)BB * HH * TT * DHH];  // f16 K   [bh][t][dh]
__device__ __half g_vt[(size_t)BB * HH * TT * DHH];  // f16 V^T [bh][dh][t]

// ---------------- helpers -------------------------------------------------------
__device__ __forceinline__ void mma_h(float* c, const uint32_t* a, const uint32_t* b) {
    asm volatile(
        "mma.sync.aligned.m16n8k16.row.col.f32.f16.f16.f32 "
        "{%0,%1,%2,%3}, {%4,%5,%6,%7}, {%8,%9}, {%0,%1,%2,%3};\n"
        : "+f"(c[0]), "+f"(c[1]), "+f"(c[2]), "+f"(c[3])
        : "r"(a[0]), "r"(a[1]), "r"(a[2]), "r"(a[3]), "r"(b[0]), "r"(b[1]));
}
__device__ __forceinline__ void ldsm4(uint32_t* r, uint32_t addr) {
    asm volatile("ldmatrix.sync.aligned.m8n8.x4.shared.b16 {%0,%1,%2,%3}, [%4];"
                 : "=r"(r[0]), "=r"(r[1]), "=r"(r[2]), "=r"(r[3]) : "r"(addr));
}
__device__ __forceinline__ void cpa16(uint32_t dst, const void* src) {
    asm volatile("cp.async.cg.shared.global [%0], [%1], 16;" :: "r"(dst), "l"(src));
}
__device__ __forceinline__ void cp_commit() { asm volatile("cp.async.commit_group;"); }
template <int N>
__device__ __forceinline__ void cp_wait() { asm volatile("cp.async.wait_group %0;" :: "n"(N)); }
__device__ __forceinline__ uint32_t h2u(__half2 h) { return *reinterpret_cast<uint32_t*>(&h); }

// ---------------- fused weight convert ------------------------------------------
// dst layout (halves): [0,3M) qkv | [3M,4M) proj | [4M,12M) gate/up INTERLEAVED
// (row chunk c of 256: rows 0-127 = gate[c*128..], 128-255 = up[c*128..]) | [12M,16M) down
__global__ void cvt_all(const float* __restrict__ wqkv, const float* __restrict__ wproj,
                        const float* __restrict__ wgate, const float* __restrict__ wup,
                        const float* __restrict__ wdown, __half* __restrict__ dst) {
    int base_idx = (blockIdx.x * 256 + threadIdx.x) * 2;
#pragma unroll
    for (int u = 0; u < 2; u++) {
        int idx = base_idx + u;                          // float4 index, 0..4M-1
        float4 v;
        int d;
        if (idx < (3 << 18)) {
            v = ((const float4*)wqkv)[idx];
            d = idx;
        } else if (idx < (4 << 18)) {
            v = ((const float4*)wproj)[idx - (3 << 18)];
            d = idx;
        } else if (idx < (8 << 18)) {
            int i = idx - (4 << 18);
            v = ((const float4*)wgate)[i];
            int j = i >> 8, c4 = i & 255;
            d = (1 << 20) + ((((j >> 7) << 8) + (j & 127)) << 8) + c4;
        } else if (idx < (12 << 18)) {
            int i = idx - (8 << 18);
            v = ((const float4*)wup)[i];
            int j = i >> 8, c4 = i & 255;
            d = (1 << 20) + ((((j >> 7) << 8) + 128 + (j & 127)) << 8) + c4;
        } else {
            v = ((const float4*)wdown)[idx - (12 << 18)];
            d = idx;
        }
        __half2 a = __floats2half2_rn(v.x, v.y);
        __half2 b = __floats2half2_rn(v.z, v.w);
        ((uint2*)dst)[d] = make_uint2(h2u(a), h2u(b));
    }
}

// ---------------- RMSNorm (f16 output) ------------------------------------------
__global__ void rmsnorm_kernel(const float* __restrict__ x,
                               const float* __restrict__ w,
                               __half* __restrict__ out) {
    int row = blockIdx.x;
    int t   = threadIdx.x;
    float4 xv = ((const float4*)(x + (size_t)row * DD))[t];
    float s = xv.x * xv.x + xv.y * xv.y + xv.z * xv.z + xv.w * xv.w;
#pragma unroll
    for (int o = 16; o; o >>= 1) s += __shfl_xor_sync(0xffffffffu, s, o);
    __shared__ float red[8];
    __shared__ float rs;
    if ((t & 31) == 0) red[t >> 5] = s;
    __syncthreads();
    if (t == 0) {
        float tot = 0.f;
#pragma unroll
        for (int i = 0; i < 8; i++) tot += red[i];
        rs = rsqrtf(tot * (1.0f / DD) + 1e-6f);
    }
    __syncthreads();
    float r = rs;
    float4 wv = ((const float4*)w)[t];
    __half2 a = __floats2half2_rn(xv.x * r * wv.x, xv.y * r * wv.y);
    __half2 b = __floats2half2_rn(xv.z * r * wv.z, xv.w * r * wv.w);
    ((uint2*)(out + (size_t)row * DD))[t] = make_uint2(h2u(a), h2u(b));
}

// ---------------- f16 tensor-core NT GEMM, 128(M) x 256(N), BK=64, 3 stages ----
// MODE 0: fp32 C (+R residual).  MODE 2: qkv scatter.  MODE 3: fused silu.
#define HST 72                                   // halves per smem row (64 + 8 pad)
#define G_AH (128 * HST)                         // A halves per stage
#define G_BH (256 * HST)                         // B halves per stage
#define G_STG ((G_AH + G_BH) * 2)                // stage bytes = 55296
#define GEMMH_SMEM (3 * G_STG)                   // 165888 B

template <int MODE>
__global__ void __launch_bounds__(512, 1)
gemm_h(const __half* __restrict__ A, const __half* __restrict__ B,
       float* __restrict__ C, const float* __restrict__ R,
       __half* __restrict__ qh, float* __restrict__ kc, float* __restrict__ vc,
       __half* __restrict__ kt, __half* __restrict__ vt, __half* __restrict__ t1,
       int M, int N, int K) {
    extern __shared__ __half smg[];
    uint32_t sbase = (uint32_t)__cvta_generic_to_shared(smg);

    int tid  = threadIdx.x;
    int warp = tid >> 5, lane = tid & 31;
    int g = lane >> 2, tig = lane & 3;
    int wm = (warp >> 2) * 32;
    int wn = (warp & 3) * 64;
    int bm = blockIdx.y * 128, bn = blockIdx.x * 256;

    // A loader: 4 thr/row, 16 halves each (2 cpa)
    int alr = tid >> 2;                 // 0..127
    int alk = (tid & 3) * 16;           // 0,16,32,48 halves
    const __half* Ag = A + (size_t)(bm + alr) * K + alk;
    uint32_t dA = (uint32_t)(alr * HST + alk) * 2;
    // B loader: 2 thr/row, 32 halves each (4 cpa)
    int blr = tid >> 1;                 // 0..255
    int blk = (tid & 1) * 32;           // 0,32 halves
    const __half* Bg = B + (size_t)(bn + blr) * K + blk;
    uint32_t dB = (uint32_t)(G_AH + blr * HST + blk) * 2;

    int aRow = wm + (lane & 15);
    int aColH = (lane >> 4) * 8;
    int bRow = (lane & 7) + ((lane >> 4) & 1) * 8;
    int bColH = ((lane >> 3) & 1) * 8;

    float acc[2][8][4];
#pragma unroll
    for (int i = 0; i < 2; i++)
#pragma unroll
        for (int j = 0; j < 8; j++)
#pragma unroll
            for (int q = 0; q < 4; q++) acc[i][j][q] = 0.f;

    auto load_chunk = [&](int chunk, int stage) {
        uint32_t so = sbase + (uint32_t)stage * G_STG;
        const __half* as = Ag + chunk * 64;
        const __half* bs = Bg + chunk * 64;
        cpa16(so + dA,      as);
        cpa16(so + dA + 16, as + 8);
#pragma unroll
        for (int i = 0; i < 4; i++) cpa16(so + dB + i * 16, bs + i * 8);
        cp_commit();
    };

    int iters = K >> 6;
    load_chunk(0, 0);
    load_chunk(1, 1);

    int rd = 0;
    for (int it = 0; it < iters; it++) {
        cp_wait<1>();
        __syncthreads();
        // refill freed stage (consumed at it-1) with chunk it+2
        if (it + 2 < iters) load_chunk(it + 2, (rd + 2) % 3);
        else cp_commit();                        // keep group accounting uniform
        // compute stage rd: 4 k16 steps
        uint32_t stA = sbase + (uint32_t)rd * G_STG;
        uint32_t stB = stA + (uint32_t)G_AH * 2;
#pragma unroll
        for (int kk = 0; kk < 4; kk++) {
            uint32_t af[2][4], bf[4][4];
#pragma unroll
            for (int mt = 0; mt < 2; mt++)
                ldsm4(af[mt], stA + (uint32_t)((aRow + mt * 16) * HST + kk * 16 + aColH) * 2);
#pragma unroll
            for (int np = 0; np < 4; np++)
                ldsm4(bf[np], stB + (uint32_t)((wn + np * 16 + bRow) * HST + kk * 16 + bColH) * 2);
#pragma unroll
            for (int mt = 0; mt < 2; mt++)
#pragma unroll
                for (int nt = 0; nt < 8; nt++)
                    mma_h(acc[mt][nt], af[mt], &bf[nt >> 1][(nt & 1) * 2]);
        }
        rd = (rd + 1) % 3;
    }

    if (MODE == 0) {
#pragma unroll
        for (int mt = 0; mt < 2; mt++) {
#pragma unroll
            for (int nt = 0; nt < 8; nt++) {
                int r0 = bm + wm + mt * 16 + g;
                int c0 = bn + wn + nt * 8 + 2 * tig;
                size_t o0 = (size_t)r0 * N + c0;
                size_t o1 = (size_t)(r0 + 8) * N + c0;
                float2 v0 = make_float2(acc[mt][nt][0], acc[mt][nt][1]);
                float2 v1 = make_float2(acc[mt][nt][2], acc[mt][nt][3]);
                float2 r4 = *(const float2*)(R + o0);
                v0.x += r4.x; v0.y += r4.y;
                float2 r5 = *(const float2*)(R + o1);
                v1.x += r5.x; v1.y += r5.y;
                *(float2*)(C + o0) = v0;
                *(float2*)(C + o1) = v1;
            }
        }
    } else if (MODE == 2) {
        int kind = bn >> 10;                    // 0=q 1=k 2=v
#pragma unroll
        for (int mt = 0; mt < 2; mt++) {
#pragma unroll
            for (int nt = 0; nt < 8; nt++) {
                int m0 = bm + wm + mt * 16 + g;
                int c0 = bn + wn + nt * 8 + 2 * tig;
                float2 v0 = make_float2(acc[mt][nt][0], acc[mt][nt][1]);
                float2 v1 = make_float2(acc[mt][nt][2], acc[mt][nt][3]);
                if (kind == 0) {
                    *(__half2*)(qh + (size_t)m0 * DD + c0) =
                        __floats2half2_rn(v0.x * 0.125f, v0.y * 0.125f);
                    *(__half2*)(qh + (size_t)(m0 + 8) * DD + c0) =
                        __floats2half2_rn(v1.x * 0.125f, v1.y * 0.125f);
                } else {
                    int cc = c0 & 1023;
                    int hh = cc >> 6, dh = cc & 63;
                    int b0 = m0 >> 11, t0 = m0 & 2047;
                    int bh = b0 * HH + hh;
                    size_t ix0 = ((size_t)bh * TT + t0) * DHH + dh;
                    size_t ix1 = ((size_t)bh * TT + t0 + 8) * DHH + dh;
                    if (kind == 1) {
                        *(float2*)(kc + ix0) = v0;
                        *(float2*)(kc + ix1) = v1;
                        *(__half2*)(kt + ix0) = __floats2half2_rn(v0.x, v0.y);
                        *(__half2*)(kt + ix1) = __floats2half2_rn(v1.x, v1.y);
                    } else {
                        *(float2*)(vc + ix0) = v0;
                        *(float2*)(vc + ix1) = v1;
                        __half* vb0 = vt + (size_t)(bh * DHH + dh) * TT + t0;
                        __half* vb1 = vt + (size_t)(bh * DHH + dh + 1) * TT + t0;
                        vb0[0] = __float2half_rn(v0.x);
                        vb1[0] = __float2half_rn(v0.y);
                        vb0[8] = __float2half_rn(v1.x);
                        vb1[8] = __float2half_rn(v1.y);
                    }
                }
            }
        }
    } else {   // MODE 3: silu fuse; cols [0,128)=gate chunk, [128,256)=up chunk
        __syncthreads();
        float* ex = (float*)smg;                // [128][132]
        if (wn >= 128) {
#pragma unroll
            for (int mt = 0; mt < 2; mt++)
#pragma unroll
                for (int nt = 0; nt < 8; nt++) {
                    int lr0 = wm + mt * 16 + g;
                    int cl = wn - 128 + nt * 8 + 2 * tig;
                    *(float2*)(ex + lr0 * 132 + cl) = make_float2(acc[mt][nt][0], acc[mt][nt][1]);
                    *(float2*)(ex + (lr0 + 8) * 132 + cl) = make_float2(acc[mt][nt][2], acc[mt][nt][3]);
                }
        }
        __syncthreads();
        if (wn < 128) {
            int tcol = (bn >> 1);
#pragma unroll
            for (int mt = 0; mt < 2; mt++)
#pragma unroll
                for (int nt = 0; nt < 8; nt++) {
                    int lr0 = wm + mt * 16 + g;
                    int cl = wn + nt * 8 + 2 * tig;
                    float2 u0 = *(const float2*)(ex + lr0 * 132 + cl);
                    float2 u1 = *(const float2*)(ex + (lr0 + 8) * 132 + cl);
                    float g0 = acc[mt][nt][0], g1 = acc[mt][nt][1];
                    float g2 = acc[mt][nt][2], g3 = acc[mt][nt][3];
                    g0 = g0 / (1.f + __expf(-g0)) * u0.x;
                    g1 = g1 / (1.f + __expf(-g1)) * u0.y;
                    g2 = g2 / (1.f + __expf(-g2)) * u1.x;
                    g3 = g3 / (1.f + __expf(-g3)) * u1.y;
                    size_t o0 = (size_t)(bm + lr0) * D4 + tcol + cl;
                    size_t o1 = (size_t)(bm + lr0 + 8) * D4 + tcol + cl;
                    *(__half2*)(t1 + o0) = __floats2half2_rn(g0, g1);
                    *(__half2*)(t1 + o1) = __floats2half2_rn(g2, g3);
                }
        }
    }
}

// ---------------- f16 tensor-core flash attention --------------------------------
#define HATR 72
#define HKVF (64 * HATR)
#define ATTH_SMEM ((4 * HKVF + 128 * HATR) * 2)
#define NEGINF __int_as_float(0xff800000)

__global__ void __launch_bounds__(256, 2)
attn_mma(const __half* __restrict__ qh, const __half* __restrict__ kt,
         const __half* __restrict__ vt, __half* __restrict__ out) {
    extern __shared__ __half smh[];
    uint32_t sbase = (uint32_t)__cvta_generic_to_shared(smh);
    const uint32_t sK = sbase;
    const uint32_t sV = sbase + 2 * HKVF * 2;
    const uint32_t sP = sbase + 4 * HKVF * 2;
    __half* pmem = smh + 4 * HKVF;

    int qt = (int)(gridDim.x - 1) - (int)blockIdx.x;
    int bh = blockIdx.y;
    int b = bh >> 4, h = bh & 15;
    int q0 = qt * 128;
    int tid = threadIdx.x;
    int warp = tid >> 5, lane = tid & 31;
    int g = lane >> 2, tig = lane & 3;
    int wm = warp * 16;

    const __half* ktb = kt + (size_t)bh * TT * DHH;
    const __half* vtb = vt + (size_t)bh * DHH * TT;

    auto load_tile = [&](int jt, int s) {
        int kv = jt * 64;
        int r = tid >> 2;
        int cbh = (tid & 3) * 16;
        const __half* ksrc = ktb + (size_t)(kv + r) * DHH + cbh;
        const __half* vsrc = vtb + (size_t)r * TT + kv + cbh;
        uint32_t kd = sK + (uint32_t)(s * HKVF + r * HATR + cbh) * 2;
        uint32_t vd = sV + (uint32_t)(s * HKVF + r * HATR + cbh) * 2;
        cpa16(kd,      ksrc);
        cpa16(kd + 16, ksrc + 8);
        cpa16(vd,      vsrc);
        cpa16(vd + 16, vsrc + 8);
    };

    {
        int row = tid >> 1;
        int part = (tid & 1) * 32;
        const __half* src = qh + (size_t)(b * TT + q0 + row) * DD + h * DHH + part;
        uint32_t dst = sP + (uint32_t)(row * HATR + part) * 2;
#pragma unroll
        for (int i = 0; i < 4; i++) cpa16(dst + i * 16, src + i * 8);
        cp_commit();
    }
    load_tile(0, 0);
    cp_commit();

    cp_wait<1>();
    __syncthreads();
    uint32_t qf[4][4];
    {
        int aRow = wm + (lane & 15);
        int aColH = (lane >> 4) * 8;
#pragma unroll
        for (int kk = 0; kk < 4; kk++)
            ldsm4(qf[kk], sP + (uint32_t)(aRow * HATR + kk * 16 + aColH) * 2);
    }
    __syncthreads();

    float o[8][4];
#pragma unroll
    for (int nt = 0; nt < 8; nt++)
#pragma unroll
        for (int i = 0; i < 4; i++) o[nt][i] = 0.f;
    float mx0 = -1e30f, mx1 = -1e30f, l0 = 0.f, l1 = 0.f;

    int nT = 2 * qt + 2;
    int bRow = (lane & 7) + ((lane >> 4) & 1) * 8;
    int bColH = ((lane >> 3) & 1) * 8;
    int aRowP = wm + (lane & 15);
    int aColP = (lane >> 4) * 8;

    for (int jt = 0; jt < nT; jt++) {
        int buf = jt & 1;
        if (jt + 1 < nT) { load_tile(jt + 1, buf ^ 1); cp_commit(); cp_wait<1>(); }
        else             { cp_commit(); cp_wait<0>(); }
        __syncthreads();

        int kv0 = jt * 64;
        if (kv0 <= q0 + wm + 15) {
            float acc[8][4];
#pragma unroll
            for (int nt = 0; nt < 8; nt++)
#pragma unroll
                for (int i = 0; i < 4; i++) acc[nt][i] = 0.f;
            uint32_t kbase = sK + (uint32_t)(buf * HKVF) * 2;
#pragma unroll
            for (int kk = 0; kk < 4; kk++) {
                uint32_t bf[4][4];
#pragma unroll
                for (int np = 0; np < 4; np++)
                    ldsm4(bf[np], kbase + (uint32_t)((np * 16 + bRow) * HATR + kk * 16 + bColH) * 2);
#pragma unroll
                for (int nt = 0; nt < 8; nt++)
                    mma_h(acc[nt], qf[kk], &bf[nt >> 1][(nt & 1) * 2]);
            }

            int row0 = q0 + wm + g, row1 = row0 + 8;
            if (kv0 + 63 > row0) {
#pragma unroll
                for (int nt = 0; nt < 8; nt++) {
                    int c = kv0 + nt * 8 + 2 * tig;
                    if (c > row0)     acc[nt][0] = NEGINF;
                    if (c + 1 > row0) acc[nt][1] = NEGINF;
                    if (c > row1)     acc[nt][2] = NEGINF;
                    if (c + 1 > row1) acc[nt][3] = NEGINF;
                }
            }

            float tm0 = NEGINF, tm1 = NEGINF;
#pragma unroll
            for (int nt = 0; nt < 8; nt++) {
                tm0 = fmaxf(tm0, fmaxf(acc[nt][0], acc[nt][1]));
                tm1 = fmaxf(tm1, fmaxf(acc[nt][2], acc[nt][3]));
            }
            tm0 = fmaxf(tm0, __shfl_xor_sync(0xffffffffu, tm0, 1));
            tm0 = fmaxf(tm0, __shfl_xor_sync(0xffffffffu, tm0, 2));
            tm1 = fmaxf(tm1, __shfl_xor_sync(0xffffffffu, tm1, 1));
            tm1 = fmaxf(tm1, __shfl_xor_sync(0xffffffffu, tm1, 2));
            float mn0 = fmaxf(mx0, tm0), mn1 = fmaxf(mx1, tm1);
            float cr0 = __expf(mx0 - mn0), cr1 = __expf(mx1 - mn1);
            mx0 = mn0; mx1 = mn1;
            float rs0 = 0.f, rs1 = 0.f;
            __half2* pr0 = (__half2*)(pmem + (wm + g) * HATR + 2 * tig);
            __half2* pr1 = (__half2*)(pmem + (wm + g + 8) * HATR + 2 * tig);
#pragma unroll
            for (int nt = 0; nt < 8; nt++) {
                __half2 p0 = __floats2half2_rn(__expf(acc[nt][0] - mn0), __expf(acc[nt][1] - mn0));
                __half2 p1 = __floats2half2_rn(__expf(acc[nt][2] - mn1), __expf(acc[nt][3] - mn1));
                pr0[nt * 4] = p0;
                pr1[nt * 4] = p1;
                float2 f0 = __half22float2(p0);
                float2 f1 = __half22float2(p1);
                rs0 += f0.x + f0.y;
                rs1 += f1.x + f1.y;
            }
            rs0 += __shfl_xor_sync(0xffffffffu, rs0, 1);
            rs0 += __shfl_xor_sync(0xffffffffu, rs0, 2);
            rs1 += __shfl_xor_sync(0xffffffffu, rs1, 1);
            rs1 += __shfl_xor_sync(0xffffffffu, rs1, 2);
            l0 = l0 * cr0 + rs0;
            l1 = l1 * cr1 + rs1;
#pragma unroll
            for (int nt = 0; nt < 8; nt++) {
                o[nt][0] *= cr0; o[nt][1] *= cr0;
                o[nt][2] *= cr1; o[nt][3] *= cr1;
            }
            __syncwarp();

            uint32_t vbase = sV + (uint32_t)(buf * HKVF) * 2;
#pragma unroll
            for (int kk = 0; kk < 4; kk++) {
                uint32_t pf[4], bv[4][4];
                ldsm4(pf, sP + (uint32_t)(aRowP * HATR + kk * 16 + aColP) * 2);
#pragma unroll
                for (int np = 0; np < 4; np++)
                    ldsm4(bv[np], vbase + (uint32_t)((np * 16 + bRow) * HATR + kk * 16 + bColH) * 2);
#pragma unroll
                for (int nt = 0; nt < 8; nt++)
                    mma_h(o[nt], pf, &bv[nt >> 1][(nt & 1) * 2]);
            }
        }
        __syncthreads();
    }

    float inv0 = 1.f / l0, inv1 = 1.f / l1;
    int r0 = q0 + wm + g;
    __half* o0 = out + (size_t)(b * TT + r0) * DD + h * DHH + 2 * tig;
    __half* o1 = o0 + (size_t)8 * DD;
#pragma unroll
    for (int nt = 0; nt < 8; nt++) {
        *(__half2*)(o0 + nt * 8) = __floats2half2_rn(o[nt][0] * inv0, o[nt][1] * inv0);
        *(__half2*)(o1 + nt * 8) = __floats2half2_rn(o[nt][2] * inv1, o[nt][3] * inv1);
    }
}

// ---------------- launch --------------------------------------------------------
extern "C" void kernel_launch(void* const* d_in, const int* in_sizes, int n_in,
                              void* d_out, int out_size) {
    const float* x       = (const float*)d_in[0];
    const float* w_norm1 = (const float*)d_in[1];
    const float* w_qkv   = (const float*)d_in[2];
    const float* w_proj  = (const float*)d_in[3];
    const float* w_norm2 = (const float*)d_in[4];
    const float* w_gate  = (const float*)d_in[5];
    const float* w_up    = (const float*)d_in[6];
    const float* w_down  = (const float*)d_in[7];

    float* xo = (float*)d_out;
    float* kc = xo + (size_t)MT * DD;
    float* vc = kc + (size_t)BB * HH * TT * DHH;

    __half *h, *qh, *att, *t1, *wh, *ktp, *vtp;
    cudaGetSymbolAddress((void**)&h,   g_h);
    cudaGetSymbolAddress((void**)&qh,  g_qh);
    cudaGetSymbolAddress((void**)&att, g_att);
    cudaGetSymbolAddress((void**)&t1,  g_t1);
    cudaGetSymbolAddress((void**)&wh,  g_wh);
    cudaGetSymbolAddress((void**)&ktp, g_kt);
    cudaGetSymbolAddress((void**)&vtp, g_vt);

    __half* wh_qkv  = wh;
    __half* wh_proj = wh + (size_t)3 * 1024 * 1024;
    __half* wh_gu   = wh + (size_t)4 * 1024 * 1024;
    __half* wh_down = wh + (size_t)12 * 1024 * 1024;

    cudaFuncSetAttribute(gemm_h<0>, cudaFuncAttributeMaxDynamicSharedMemorySize, GEMMH_SMEM);
    cudaFuncSetAttribute(gemm_h<2>, cudaFuncAttributeMaxDynamicSharedMemorySize, GEMMH_SMEM);
    cudaFuncSetAttribute(gemm_h<3>, cudaFuncAttributeMaxDynamicSharedMemorySize, GEMMH_SMEM);
    cudaFuncSetAttribute(attn_mma,  cudaFuncAttributeMaxDynamicSharedMemorySize, ATTH_SMEM);

    // 0. convert all weights (gate/up interleaved)
    cvt_all<<<(16 * 1024 * 1024 / 8) / 256, 256>>>(w_qkv, w_proj, w_gate, w_up, w_down, wh);

    // 1. h = f16(rmsnorm(x) * w1)
    rmsnorm_kernel<<<MT, 256>>>(x, w_norm1, h);
    // 2. qkv GEMM with fused scatter: q->qh (f16, scaled), k/v->caches + kt/vt
    gemm_h<2><<<dim3(D3 / 256, MT / 128), 512, GEMMH_SMEM>>>(
        h, wh_qkv, nullptr, nullptr, qh, kc, vc, ktp, vtp, nullptr, MT, D3, DD);
    // 3. f16 causal flash attention -> att
    attn_mma<<<dim3(TT / 128, BB * HH), 256, ATTH_SMEM>>>(qh, ktp, vtp, att);
    // 4. x = x + att @ w_proj^T
    gemm_h<0><<<dim3(DD / 256, MT / 128), 512, GEMMH_SMEM>>>(
        att, wh_proj, xo, x, nullptr, nullptr, nullptr, nullptr, nullptr, nullptr, MT, DD, DD);
    // 5. h = f16(rmsnorm(x) * w2)
    rmsnorm_kernel<<<MT, 256>>>(xo, w_norm2, h);
    // 6. gate/up GEMM with fused silu -> t1 (f16)
    gemm_h<3><<<dim3(D8 / 256, MT / 128), 512, GEMMH_SMEM>>>(
        h, wh_gu, nullptr, nullptr, nullptr, nullptr, nullptr, nullptr, nullptr, t1, MT, D8, DD);
    // 7. x += t1 @ w_down^T
    gemm_h<0><<<dim3(DD / 256, MT / 128), 512, GEMMH_SMEM>>>(
        t1, wh_down, xo, xo, nullptr, nullptr, nullptr, nullptr, nullptr, nullptr, MT, DD, D4);
}

// round 10
// speedup vs baseline: 1.1904x; 1.1904x over previous
#include <cuda_runtime.h>
#include <cuda_fp16.h>
#include <math.h>
#include <stdint.h>

#define BB   2
#define TT   2048
#define DD   1024
#define HH   16
#define DHH  64
#define MT   4096            // B*T
#define D3   3072            // 3*D
#define D4   4096            // 4*D
#define D8   8192            // gate+up stacked

// ---------------- scratch (static device arrays; no allocation) ----------------
__device__ __half g_h[MT * DD];                      // rmsnorm output (f16)
__device__ __half g_qh[MT * DD];                     // q, f16, pre-scaled by 1/8
__device__ __half g_att[MT * DD];                    // attention out (f16)
__device__ __half g_t1[(size_t)MT * D4];             // silu(gate)*up (f16)
__device__ __half g_wh[16 * 1024 * 1024];            // converted weights (f16)
__device__ __half g_kt[(size_t)BB * HH * TT * DHH];  // f16 K   [bh][t][dh]
__device__ __half g_vt[(size_t)BB * HH * TT * DHH];  // f16 V^T [bh][dh][t]

// ---------------- helpers -------------------------------------------------------
__device__ __forceinline__ void mma_h(float* c, const uint32_t* a, const uint32_t* b) {
    asm volatile(
        "mma.sync.aligned.m16n8k16.row.col.f32.f16.f16.f32 "
        "{%0,%1,%2,%3}, {%4,%5,%6,%7}, {%8,%9}, {%0,%1,%2,%3};\n"
        : "+f"(c[0]), "+f"(c[1]), "+f"(c[2]), "+f"(c[3])
        : "r"(a[0]), "r"(a[1]), "r"(a[2]), "r"(a[3]), "r"(b[0]), "r"(b[1]));
}
__device__ __forceinline__ void ldsm4(uint32_t* r, uint32_t addr) {
    asm volatile("ldmatrix.sync.aligned.m8n8.x4.shared.b16 {%0,%1,%2,%3}, [%4];"
                 : "=r"(r[0]), "=r"(r[1]), "=r"(r[2]), "=r"(r[3]) : "r"(addr));
}
__device__ __forceinline__ void cpa16(uint32_t dst, const void* src) {
    asm volatile("cp.async.cg.shared.global [%0], [%1], 16;" :: "r"(dst), "l"(src));
}
__device__ __forceinline__ void cp_commit() { asm volatile("cp.async.commit_group;"); }
template <int N>
__device__ __forceinline__ void cp_wait() { asm volatile("cp.async.wait_group %0;" :: "n"(N)); }
__device__ __forceinline__ uint32_t h2u(__half2 h) { return *reinterpret_cast<uint32_t*>(&h); }

// ---------------- fused weight convert ------------------------------------------
// dst layout (halves): [0,3M) qkv | [3M,4M) proj | [4M,12M) gate/up INTERLEAVED
// (row chunk c of 256: rows 0-127 = gate[c*128..], 128-255 = up[c*128..]) | [12M,16M) down
__global__ void cvt_all(const float* __restrict__ wqkv, const float* __restrict__ wproj,
                        const float* __restrict__ wgate, const float* __restrict__ wup,
                        const float* __restrict__ wdown, __half* __restrict__ dst) {
    int base_idx = (blockIdx.x * 256 + threadIdx.x) * 2;
#pragma unroll
    for (int u = 0; u < 2; u++) {
        int idx = base_idx + u;                          // float4 index, 0..4M-1
        float4 v;
        int d;
        if (idx < (3 << 18)) {
            v = ((const float4*)wqkv)[idx];
            d = idx;
        } else if (idx < (4 << 18)) {
            v = ((const float4*)wproj)[idx - (3 << 18)];
            d = idx;
        } else if (idx < (8 << 18)) {
            int i = idx - (4 << 18);
            v = ((const float4*)wgate)[i];
            int j = i >> 8, c4 = i & 255;
            d = (1 << 20) + ((((j >> 7) << 8) + (j & 127)) << 8) + c4;
        } else if (idx < (12 << 18)) {
            int i = idx - (8 << 18);
            v = ((const float4*)wup)[i];
            int j = i >> 8, c4 = i & 255;
            d = (1 << 20) + ((((j >> 7) << 8) + 128 + (j & 127)) << 8) + c4;
        } else {
            v = ((const float4*)wdown)[idx - (12 << 18)];
            d = idx;
        }
        __half2 a = __floats2half2_rn(v.x, v.y);
        __half2 b = __floats2half2_rn(v.z, v.w);
        ((uint2*)dst)[d] = make_uint2(h2u(a), h2u(b));
    }
}

// ---------------- RMSNorm (f16 output) ------------------------------------------
__global__ void rmsnorm_kernel(const float* __restrict__ x,
                               const float* __restrict__ w,
                               __half* __restrict__ out) {
    int row = blockIdx.x;
    int t   = threadIdx.x;
    float4 xv = ((const float4*)(x + (size_t)row * DD))[t];
    float s = xv.x * xv.x + xv.y * xv.y + xv.z * xv.z + xv.w * xv.w;
#pragma unroll
    for (int o = 16; o; o >>= 1) s += __shfl_xor_sync(0xffffffffu, s, o);
    __shared__ float red[8];
    __shared__ float rs;
    if ((t & 31) == 0) red[t >> 5] = s;
    __syncthreads();
    if (t == 0) {
        float tot = 0.f;
#pragma unroll
        for (int i = 0; i < 8; i++) tot += red[i];
        rs = rsqrtf(tot * (1.0f / DD) + 1e-6f);
    }
    __syncthreads();
    float r = rs;
    float4 wv = ((const float4*)w)[t];
    __half2 a = __floats2half2_rn(xv.x * r * wv.x, xv.y * r * wv.y);
    __half2 b = __floats2half2_rn(xv.z * r * wv.z, xv.w * r * wv.w);
    ((uint2*)(out + (size_t)row * DD))[t] = make_uint2(h2u(a), h2u(b));
}

// ---------------- f16 tensor-core NT GEMM, 128(M) x 256(N) tiles ----------------
// MODE 0: fp32 C (+R residual).  MODE 2: qkv scatter (q f16 scaled / caches / kt / vt).
// MODE 3: fused silu(gate)*up -> t1 f16 (gate/up interleaved weights).
// BK=32, 6-stage cp.async pipeline (deep: covers L2/DRAM latency at 1 CTA/SM).
#define HST 40
#define HSTG 6
#define G_AH (128 * HST)
#define G_BH (256 * HST)
#define GEMMH_SMEM (HSTG * (G_AH + G_BH) * 2)   // 184320 B

template <int MODE>
__global__ void __launch_bounds__(512, 1)
gemm_h(const __half* __restrict__ A, const __half* __restrict__ B,
       float* __restrict__ C, const float* __restrict__ R,
       __half* __restrict__ qh, float* __restrict__ kc, float* __restrict__ vc,
       __half* __restrict__ kt, __half* __restrict__ vt, __half* __restrict__ t1,
       int M, int N, int K) {
    extern __shared__ __half smg[];
    uint32_t sA = (uint32_t)__cvta_generic_to_shared(smg);
    uint32_t sB = sA + HSTG * G_AH * 2;

    int tid  = threadIdx.x;
    int warp = tid >> 5, lane = tid & 31;
    int g = lane >> 2, tig = lane & 3;
    int wm = (warp >> 2) * 32;
    int wn = (warp & 3) * 64;
    int bm = blockIdx.y * 128, bn = blockIdx.x * 256;

    int alr = tid >> 2;
    int alk = (tid & 3) * 8;
    const __half* Ag = A + (size_t)(bm + alr) * K + alk;
    uint32_t dA = sA + (uint32_t)(alr * HST + alk) * 2;
    int blr = tid >> 1;
    int blk = (tid & 1) * 16;
    const __half* Bg = B + (size_t)(bn + blr) * K + blk;
    uint32_t dB = sB + (uint32_t)(blr * HST + blk) * 2;

    int aRow = wm + (lane & 15);
    int aColH = (lane >> 4) * 8;
    int bRow = (lane & 7) + ((lane >> 4) & 1) * 8;
    int bColH = ((lane >> 3) & 1) * 8;

    float acc[2][8][4];
#pragma unroll
    for (int i = 0; i < 2; i++)
#pragma unroll
        for (int j = 0; j < 8; j++)
#pragma unroll
            for (int q = 0; q < 4; q++) acc[i][j][q] = 0.f;

#pragma unroll
    for (int s = 0; s < HSTG - 1; s++) {
        uint32_t ao = (uint32_t)(s * G_AH * 2);
        uint32_t bo = (uint32_t)(s * G_BH * 2);
        int ko = s * 32;
        cpa16(dA + ao,      Ag + ko);
        cpa16(dB + bo,      Bg + ko);
        cpa16(dB + bo + 16, Bg + ko + 8);
        cp_commit();
    }

    int rd = 0, wr = HSTG - 1;
    int iters = K >> 5;
    cp_wait<HSTG - 2>();
    __syncthreads();

    for (int it = 0; it < iters; it++) {
        uint32_t stA = sA + (uint32_t)(rd * G_AH * 2);
        uint32_t stB = sB + (uint32_t)(rd * G_BH * 2);
#pragma unroll
        for (int kk = 0; kk < 2; kk++) {
            uint32_t af[2][4], bf[4][4];
#pragma unroll
            for (int mt = 0; mt < 2; mt++)
                ldsm4(af[mt], stA + (uint32_t)((aRow + mt * 16) * HST + kk * 16 + aColH) * 2);
#pragma unroll
            for (int np = 0; np < 4; np++)
                ldsm4(bf[np], stB + (uint32_t)((wn + np * 16 + bRow) * HST + kk * 16 + bColH) * 2);
#pragma unroll
            for (int mt = 0; mt < 2; mt++)
#pragma unroll
                for (int nt = 0; nt < 8; nt++)
                    mma_h(acc[mt][nt], af[mt], &bf[nt >> 1][(nt & 1) * 2]);
        }
        int nk = (it + HSTG - 1) * 32;
        if (nk < K) {
            uint32_t ao = (uint32_t)(wr * G_AH * 2);
            uint32_t bo = (uint32_t)(wr * G_BH * 2);
            cpa16(dA + ao,      Ag + nk);
            cpa16(dB + bo,      Bg + nk);
            cpa16(dB + bo + 16, Bg + nk + 8);
        }
        cp_commit();
        wr = rd;
        rd = (rd + 1 == HSTG) ? 0 : rd + 1;
        cp_wait<HSTG - 2>();
        __syncthreads();
    }

    if (MODE == 0) {
#pragma unroll
        for (int mt = 0; mt < 2; mt++) {
#pragma unroll
            for (int nt = 0; nt < 8; nt++) {
                int r0 = bm + wm + mt * 16 + g;
                int c0 = bn + wn + nt * 8 + 2 * tig;
                size_t o0 = (size_t)r0 * N + c0;
                size_t o1 = (size_t)(r0 + 8) * N + c0;
                float2 v0 = make_float2(acc[mt][nt][0], acc[mt][nt][1]);
                float2 v1 = make_float2(acc[mt][nt][2], acc[mt][nt][3]);
                float2 r4 = *(const float2*)(R + o0);
                v0.x += r4.x; v0.y += r4.y;
                float2 r5 = *(const float2*)(R + o1);
                v1.x += r5.x; v1.y += r5.y;
                *(float2*)(C + o0) = v0;
                *(float2*)(C + o1) = v1;
            }
        }
    } else if (MODE == 2) {
        int kind = bn >> 10;                    // 0=q 1=k 2=v
#pragma unroll
        for (int mt = 0; mt < 2; mt++) {
#pragma unroll
            for (int nt = 0; nt < 8; nt++) {
                int m0 = bm + wm + mt * 16 + g;
                int c0 = bn + wn + nt * 8 + 2 * tig;
                float2 v0 = make_float2(acc[mt][nt][0], acc[mt][nt][1]);
                float2 v1 = make_float2(acc[mt][nt][2], acc[mt][nt][3]);
                if (kind == 0) {
                    *(__half2*)(qh + (size_t)m0 * DD + c0) =
                        __floats2half2_rn(v0.x * 0.125f, v0.y * 0.125f);
                    *(__half2*)(qh + (size_t)(m0 + 8) * DD + c0) =
                        __floats2half2_rn(v1.x * 0.125f, v1.y * 0.125f);
                } else {
                    int cc = c0 & 1023;
                    int hh = cc >> 6, dh = cc & 63;
                    int b0 = m0 >> 11, t0 = m0 & 2047;
                    int bh = b0 * HH + hh;
                    size_t ix0 = ((size_t)bh * TT + t0) * DHH + dh;
                    size_t ix1 = ((size_t)bh * TT + t0 + 8) * DHH + dh;
                    if (kind == 1) {
                        *(float2*)(kc + ix0) = v0;
                        *(float2*)(kc + ix1) = v1;
                        *(__half2*)(kt + ix0) = __floats2half2_rn(v0.x, v0.y);
                        *(__half2*)(kt + ix1) = __floats2half2_rn(v1.x, v1.y);
                    } else {
                        *(float2*)(vc + ix0) = v0;
                        *(float2*)(vc + ix1) = v1;
                        __half* vb0 = vt + (size_t)(bh * DHH + dh) * TT + t0;
                        __half* vb1 = vt + (size_t)(bh * DHH + dh + 1) * TT + t0;
                        vb0[0] = __float2half_rn(v0.x);
                        vb1[0] = __float2half_rn(v0.y);
                        vb0[8] = __float2half_rn(v1.x);
                        vb1[8] = __float2half_rn(v1.y);
                    }
                }
            }
        }
    } else {   // MODE 3: silu fuse; cols [0,128)=gate chunk, [128,256)=up chunk
        __syncthreads();                        // cp.async data consumed; reuse smem
        float* ex = (float*)smg;                // [128][132]
        if (wn >= 128) {
#pragma unroll
            for (int mt = 0; mt < 2; mt++)
#pragma unroll
                for (int nt = 0; nt < 8; nt++) {
                    int lr0 = wm + mt * 16 + g;
                    int cl = wn - 128 + nt * 8 + 2 * tig;
                    *(float2*)(ex + lr0 * 132 + cl) = make_float2(acc[mt][nt][0], acc[mt][nt][1]);
                    *(float2*)(ex + (lr0 + 8) * 132 + cl) = make_float2(acc[mt][nt][2], acc[mt][nt][3]);
                }
        }
        __syncthreads();
        if (wn < 128) {
            int tcol = (bn >> 1);               // output column base = chunk*128
#pragma unroll
            for (int mt = 0; mt < 2; mt++)
#pragma unroll
                for (int nt = 0; nt < 8; nt++) {
                    int lr0 = wm + mt * 16 + g;
                    int cl = wn + nt * 8 + 2 * tig;
                    float2 u0 = *(const float2*)(ex + lr0 * 132 + cl);
                    float2 u1 = *(const float2*)(ex + (lr0 + 8) * 132 + cl);
                    float g0 = acc[mt][nt][0], g1 = acc[mt][nt][1];
                    float g2 = acc[mt][nt][2], g3 = acc[mt][nt][3];
                    g0 = g0 / (1.f + __expf(-g0)) * u0.x;
                    g1 = g1 / (1.f + __expf(-g1)) * u0.y;
                    g2 = g2 / (1.f + __expf(-g2)) * u1.x;
                    g3 = g3 / (1.f + __expf(-g3)) * u1.y;
                    size_t o0 = (size_t)(bm + lr0) * D4 + tcol + cl;
                    size_t o1 = (size_t)(bm + lr0 + 8) * D4 + tcol + cl;
                    *(__half2*)(t1 + o0) = __floats2half2_rn(g0, g1);
                    *(__half2*)(t1 + o1) = __floats2half2_rn(g2, g3);
                }
        }
    }
}

// ---------------- f16 tensor-core flash attention --------------------------------
#define HATR 72
#define HKVF (64 * HATR)
#define ATTH_SMEM ((4 * HKVF + 128 * HATR) * 2)
#define NEGINF __int_as_float(0xff800000)

__global__ void __launch_bounds__(256, 2)
attn_mma(const __half* __restrict__ qh, const __half* __restrict__ kt,
         const __half* __restrict__ vt, __half* __restrict__ out) {
    extern __shared__ __half smh[];
    uint32_t sbase = (uint32_t)__cvta_generic_to_shared(smh);
    const uint32_t sK = sbase;
    const uint32_t sV = sbase + 2 * HKVF * 2;
    const uint32_t sP = sbase + 4 * HKVF * 2;
    __half* pmem = smh + 4 * HKVF;

    int qt = (int)(gridDim.x - 1) - (int)blockIdx.x;
    int bh = blockIdx.y;
    int b = bh >> 4, h = bh & 15;
    int q0 = qt * 128;
    int tid = threadIdx.x;
    int warp = tid >> 5, lane = tid & 31;
    int g = lane >> 2, tig = lane & 3;
    int wm = warp * 16;

    const __half* ktb = kt + (size_t)bh * TT * DHH;
    const __half* vtb = vt + (size_t)bh * DHH * TT;

    auto load_tile = [&](int jt, int s) {
        int kv = jt * 64;
        int r = tid >> 2;
        int cbh = (tid & 3) * 16;
        const __half* ksrc = ktb + (size_t)(kv + r) * DHH + cbh;
        const __half* vsrc = vtb + (size_t)r * TT + kv + cbh;
        uint32_t kd = sK + (uint32_t)(s * HKVF + r * HATR + cbh) * 2;
        uint32_t vd = sV + (uint32_t)(s * HKVF + r * HATR + cbh) * 2;
        cpa16(kd,      ksrc);
        cpa16(kd + 16, ksrc + 8);
        cpa16(vd,      vsrc);
        cpa16(vd + 16, vsrc + 8);
    };

    {
        int row = tid >> 1;
        int part = (tid & 1) * 32;
        const __half* src = qh + (size_t)(b * TT + q0 + row) * DD + h * DHH + part;
        uint32_t dst = sP + (uint32_t)(row * HATR + part) * 2;
#pragma unroll
        for (int i = 0; i < 4; i++) cpa16(dst + i * 16, src + i * 8);
        cp_commit();
    }
    load_tile(0, 0);
    cp_commit();

    cp_wait<1>();
    __syncthreads();
    uint32_t qf[4][4];
    {
        int aRow = wm + (lane & 15);
        int aColH = (lane >> 4) * 8;
#pragma unroll
        for (int kk = 0; kk < 4; kk++)
            ldsm4(qf[kk], sP + (uint32_t)(aRow * HATR + kk * 16 + aColH) * 2);
    }
    __syncthreads();

    float o[8][4];
#pragma unroll
    for (int nt = 0; nt < 8; nt++)
#pragma unroll
        for (int i = 0; i < 4; i++) o[nt][i] = 0.f;
    float mx0 = -1e30f, mx1 = -1e30f, l0 = 0.f, l1 = 0.f;

    int nT = 2 * qt + 2;
    int bRow = (lane & 7) + ((lane >> 4) & 1) * 8;
    int bColH = ((lane >> 3) & 1) * 8;
    int aRowP = wm + (lane & 15);
    int aColP = (lane >> 4) * 8;

    for (int jt = 0; jt < nT; jt++) {
        int buf = jt & 1;
        if (jt + 1 < nT) { load_tile(jt + 1, buf ^ 1); cp_commit(); cp_wait<1>(); }
        else             { cp_commit(); cp_wait<0>(); }
        __syncthreads();

        int kv0 = jt * 64;
        if (kv0 <= q0 + wm + 15) {
            float acc[8][4];
#pragma unroll
            for (int nt = 0; nt < 8; nt++)
#pragma unroll
                for (int i = 0; i < 4; i++) acc[nt][i] = 0.f;
            uint32_t kbase = sK + (uint32_t)(buf * HKVF) * 2;
#pragma unroll
            for (int kk = 0; kk < 4; kk++) {
                uint32_t bf[4][4];
#pragma unroll
                for (int np = 0; np < 4; np++)
                    ldsm4(bf[np], kbase + (uint32_t)((np * 16 + bRow) * HATR + kk * 16 + bColH) * 2);
#pragma unroll
                for (int nt = 0; nt < 8; nt++)
                    mma_h(acc[nt], qf[kk], &bf[nt >> 1][(nt & 1) * 2]);
            }

            int row0 = q0 + wm + g, row1 = row0 + 8;
            if (kv0 + 63 > row0) {
#pragma unroll
                for (int nt = 0; nt < 8; nt++) {
                    int c = kv0 + nt * 8 + 2 * tig;
                    if (c > row0)     acc[nt][0] = NEGINF;
                    if (c + 1 > row0) acc[nt][1] = NEGINF;
                    if (c > row1)     acc[nt][2] = NEGINF;
                    if (c + 1 > row1) acc[nt][3] = NEGINF;
                }
            }

            float tm0 = NEGINF, tm1 = NEGINF;
#pragma unroll
            for (int nt = 0; nt < 8; nt++) {
                tm0 = fmaxf(tm0, fmaxf(acc[nt][0], acc[nt][1]));
                tm1 = fmaxf(tm1, fmaxf(acc[nt][2], acc[nt][3]));
            }
            tm0 = fmaxf(tm0, __shfl_xor_sync(0xffffffffu, tm0, 1));
            tm0 = fmaxf(tm0, __shfl_xor_sync(0xffffffffu, tm0, 2));
            tm1 = fmaxf(tm1, __shfl_xor_sync(0xffffffffu, tm1, 1));
            tm1 = fmaxf(tm1, __shfl_xor_sync(0xffffffffu, tm1, 2));
            float mn0 = fmaxf(mx0, tm0), mn1 = fmaxf(mx1, tm1);
            float cr0 = __expf(mx0 - mn0), cr1 = __expf(mx1 - mn1);
            mx0 = mn0; mx1 = mn1;
            float rs0 = 0.f, rs1 = 0.f;
            __half2* pr0 = (__half2*)(pmem + (wm + g) * HATR + 2 * tig);
            __half2* pr1 = (__half2*)(pmem + (wm + g + 8) * HATR + 2 * tig);
#pragma unroll
            for (int nt = 0; nt < 8; nt++) {
                __half2 p0 = __floats2half2_rn(__expf(acc[nt][0] - mn0), __expf(acc[nt][1] - mn0));
                __half2 p1 = __floats2half2_rn(__expf(acc[nt][2] - mn1), __expf(acc[nt][3] - mn1));
                pr0[nt * 4] = p0;
                pr1[nt * 4] = p1;
                float2 f0 = __half22float2(p0);
                float2 f1 = __half22float2(p1);
                rs0 += f0.x + f0.y;
                rs1 += f1.x + f1.y;
            }
            rs0 += __shfl_xor_sync(0xffffffffu, rs0, 1);
            rs0 += __shfl_xor_sync(0xffffffffu, rs0, 2);
            rs1 += __shfl_xor_sync(0xffffffffu, rs1, 1);
            rs1 += __shfl_xor_sync(0xffffffffu, rs1, 2);
            l0 = l0 * cr0 + rs0;
            l1 = l1 * cr1 + rs1;
#pragma unroll
            for (int nt = 0; nt < 8; nt++) {
                o[nt][0] *= cr0; o[nt][1] *= cr0;
                o[nt][2] *= cr1; o[nt][3] *= cr1;
            }
            __syncwarp();

            uint32_t vbase = sV + (uint32_t)(buf * HKVF) * 2;
#pragma unroll
            for (int kk = 0; kk < 4; kk++) {
                uint32_t pf[4], bv[4][4];
                ldsm4(pf, sP + (uint32_t)(aRowP * HATR + kk * 16 + aColP) * 2);
#pragma unroll
                for (int np = 0; np < 4; np++)
                    ldsm4(bv[np], vbase + (uint32_t)((np * 16 + bRow) * HATR + kk * 16 + bColH) * 2);
#pragma unroll
                for (int nt = 0; nt < 8; nt++)
                    mma_h(o[nt], pf, &bv[nt >> 1][(nt & 1) * 2]);
            }
        }
        __syncthreads();
    }

    float inv0 = 1.f / l0, inv1 = 1.f / l1;
    int r0 = q0 + wm + g;
    __half* o0 = out + (size_t)(b * TT + r0) * DD + h * DHH + 2 * tig;
    __half* o1 = o0 + (size_t)8 * DD;
#pragma unroll
    for (int nt = 0; nt < 8; nt++) {
        *(__half2*)(o0 + nt * 8) = __floats2half2_rn(o[nt][0] * inv0, o[nt][1] * inv0);
        *(__half2*)(o1 + nt * 8) = __floats2half2_rn(o[nt][2] * inv1, o[nt][3] * inv1);
    }
}

// ---------------- launch --------------------------------------------------------
extern "C" void kernel_launch(void* const* d_in, const int* in_sizes, int n_in,
                              void* d_out, int out_size) {
    const float* x       = (const float*)d_in[0];
    const float* w_norm1 = (const float*)d_in[1];
    const float* w_qkv   = (const float*)d_in[2];
    const float* w_proj  = (const float*)d_in[3];
    const float* w_norm2 = (const float*)d_in[4];
    const float* w_gate  = (const float*)d_in[5];
    const float* w_up    = (const float*)d_in[6];
    const float* w_down  = (const float*)d_in[7];

    float* xo = (float*)d_out;
    float* kc = xo + (size_t)MT * DD;
    float* vc = kc + (size_t)BB * HH * TT * DHH;

    __half *h, *qh, *att, *t1, *wh, *ktp, *vtp;
    cudaGetSymbolAddress((void**)&h,   g_h);
    cudaGetSymbolAddress((void**)&qh,  g_qh);
    cudaGetSymbolAddress((void**)&att, g_att);
    cudaGetSymbolAddress((void**)&t1,  g_t1);
    cudaGetSymbolAddress((void**)&wh,  g_wh);
    cudaGetSymbolAddress((void**)&ktp, g_kt);
    cudaGetSymbolAddress((void**)&vtp, g_vt);

    __half* wh_qkv  = wh;
    __half* wh_proj = wh + (size_t)3 * 1024 * 1024;
    __half* wh_gu   = wh + (size_t)4 * 1024 * 1024;
    __half* wh_down = wh + (size_t)12 * 1024 * 1024;

    cudaFuncSetAttribute(gemm_h<0>, cudaFuncAttributeMaxDynamicSharedMemorySize, GEMMH_SMEM);
    cudaFuncSetAttribute(gemm_h<2>, cudaFuncAttributeMaxDynamicSharedMemorySize, GEMMH_SMEM);
    cudaFuncSetAttribute(gemm_h<3>, cudaFuncAttributeMaxDynamicSharedMemorySize, GEMMH_SMEM);
    cudaFuncSetAttribute(attn_mma,  cudaFuncAttributeMaxDynamicSharedMemorySize, ATTH_SMEM);

    // 0. convert all weights (gate/up interleaved)
    cvt_all<<<(16 * 1024 * 1024 / 8) / 256, 256>>>(w_qkv, w_proj, w_gate, w_up, w_down, wh);

    // 1. h = f16(rmsnorm(x) * w1)
    rmsnorm_kernel<<<MT, 256>>>(x, w_norm1, h);
    // 2. qkv GEMM with fused scatter: q->qh (f16, scaled), k/v->caches + kt/vt
    gemm_h<2><<<dim3(D3 / 256, MT / 128), 512, GEMMH_SMEM>>>(
        h, wh_qkv, nullptr, nullptr, qh, kc, vc, ktp, vtp, nullptr, MT, D3, DD);
    // 3. f16 causal flash attention -> att
    attn_mma<<<dim3(TT / 128, BB * HH), 256, ATTH_SMEM>>>(qh, ktp, vtp, att);
    // 4. x = x + att @ w_proj^T
    gemm_h<0><<<dim3(DD / 256, MT / 128), 512, GEMMH_SMEM>>>(
        att, wh_proj, xo, x, nullptr, nullptr, nullptr, nullptr, nullptr, nullptr, MT, DD, DD);
    // 5. h = f16(rmsnorm(x) * w2)
    rmsnorm_kernel<<<MT, 256>>>(xo, w_norm2, h);
    // 6. gate/up GEMM with fused silu -> t1 (f16)
    gemm_h<3><<<dim3(D8 / 256, MT / 128), 512, GEMMH_SMEM>>>(
        h, wh_gu, nullptr, nullptr, nullptr, nullptr, nullptr, nullptr, nullptr, t1, MT, D8, DD);
    // 7. x += t1 @ w_down^T
    gemm_h<0><<<dim3(DD / 256, MT / 128), 512, GEMMH_SMEM>>>(
        t1, wh_down, xo, xo, nullptr, nullptr, nullptr, nullptr, nullptr, nullptr, MT, DD, D4);
}

// round 12
// speedup vs baseline: 1.2300x; 1.0333x over previous
#include <cuda_runtime.h>
#include <cuda_fp16.h>
#include <math.h>
#include <stdint.h>

#define BB   2
#define TT   2048
#define DD   1024
#define HH   16
#define DHH  64
#define MT   4096            // B*T
#define D3   3072            // 3*D
#define D4   4096            // 4*D
#define D8   8192            // gate+up stacked

// ---------------- scratch (static device arrays; no allocation) ----------------
__device__ __half g_h[MT * DD];                      // rmsnorm output (f16)
__device__ __half g_qh[MT * DD];                     // q, f16, pre-scaled by 1/8
__device__ __half g_att[MT * DD];                    // attention out (f16)
__device__ __half g_t1[(size_t)MT * D4];             // silu(gate)*up (f16)
__device__ __half g_wh[16 * 1024 * 1024];            // converted weights (f16)
__device__ __half g_kt[(size_t)BB * HH * TT * DHH];  // f16 K   [bh][t][dh]
__device__ __half g_vt[(size_t)BB * HH * TT * DHH];  // f16 V^T [bh][dh][t]

// ---------------- helpers -------------------------------------------------------
__device__ __forceinline__ void mma_h(float* c, const uint32_t* a, const uint32_t* b) {
    asm volatile(
        "mma.sync.aligned.m16n8k16.row.col.f32.f16.f16.f32 "
        "{%0,%1,%2,%3}, {%4,%5,%6,%7}, {%8,%9}, {%0,%1,%2,%3};\n"
        : "+f"(c[0]), "+f"(c[1]), "+f"(c[2]), "+f"(c[3])
        : "r"(a[0]), "r"(a[1]), "r"(a[2]), "r"(a[3]), "r"(b[0]), "r"(b[1]));
}
__device__ __forceinline__ void ldsm4(uint32_t* r, uint32_t addr) {
    asm volatile("ldmatrix.sync.aligned.m8n8.x4.shared.b16 {%0,%1,%2,%3}, [%4];"
                 : "=r"(r[0]), "=r"(r[1]), "=r"(r[2]), "=r"(r[3]) : "r"(addr));
}
__device__ __forceinline__ void cpa16(uint32_t dst, const void* src) {
    asm volatile("cp.async.cg.shared.global [%0], [%1], 16;" :: "r"(dst), "l"(src));
}
__device__ __forceinline__ void cp_commit() { asm volatile("cp.async.commit_group;"); }
template <int N>
__device__ __forceinline__ void cp_wait() { asm volatile("cp.async.wait_group %0;" :: "n"(N)); }
__device__ __forceinline__ uint32_t h2u(__half2 h) { return *reinterpret_cast<uint32_t*>(&h); }

// ---------------- fused weight convert ------------------------------------------
// dst layout (halves): [0,3M) qkv | [3M,4M) proj | [4M,12M) gate/up INTERLEAVED
// (row chunk c of 256: rows 0-127 = gate[c*128..], 128-255 = up[c*128..]) | [12M,16M) down
__global__ void cvt_all(const float* __restrict__ wqkv, const float* __restrict__ wproj,
                        const float* __restrict__ wgate, const float* __restrict__ wup,
                        const float* __restrict__ wdown, __half* __restrict__ dst) {
    int base_idx = (blockIdx.x * 256 + threadIdx.x) * 4;
#pragma unroll
    for (int u = 0; u < 4; u++) {
        int idx = base_idx + u;                          // float4 index, 0..4M-1
        float4 v;
        int d;
        if (idx < (3 << 18)) {
            v = ((const float4*)wqkv)[idx];
            d = idx;
        } else if (idx < (4 << 18)) {
            v = ((const float4*)wproj)[idx - (3 << 18)];
            d = idx;
        } else if (idx < (8 << 18)) {
            int i = idx - (4 << 18);
            v = ((const float4*)wgate)[i];
            int j = i >> 8, c4 = i & 255;
            d = (1 << 20) + ((((j >> 7) << 8) + (j & 127)) << 8) + c4;
        } else if (idx < (12 << 18)) {
            int i = idx - (8 << 18);
            v = ((const float4*)wup)[i];
            int j = i >> 8, c4 = i & 255;
            d = (1 << 20) + ((((j >> 7) << 8) + 128 + (j & 127)) << 8) + c4;
        } else {
            v = ((const float4*)wdown)[idx - (12 << 18)];
            d = idx;
        }
        __half2 a = __floats2half2_rn(v.x, v.y);
        __half2 b = __floats2half2_rn(v.z, v.w);
        ((uint2*)dst)[d] = make_uint2(h2u(a), h2u(b));
    }
}

// ---------------- RMSNorm (f16 output) ------------------------------------------
__global__ void rmsnorm_kernel(const float* __restrict__ x,
                               const float* __restrict__ w,
                               __half* __restrict__ out) {
    int row = blockIdx.x;
    int t   = threadIdx.x;
    float4 xv = ((const float4*)(x + (size_t)row * DD))[t];
    float s = xv.x * xv.x + xv.y * xv.y + xv.z * xv.z + xv.w * xv.w;
#pragma unroll
    for (int o = 16; o; o >>= 1) s += __shfl_xor_sync(0xffffffffu, s, o);
    __shared__ float red[8];
    __shared__ float rs;
    if ((t & 31) == 0) red[t >> 5] = s;
    __syncthreads();
    if (t == 0) {
        float tot = 0.f;
#pragma unroll
        for (int i = 0; i < 8; i++) tot += red[i];
        rs = rsqrtf(tot * (1.0f / DD) + 1e-6f);
    }
    __syncthreads();
    float r = rs;
    float4 wv = ((const float4*)w)[t];
    __half2 a = __floats2half2_rn(xv.x * r * wv.x, xv.y * r * wv.y);
    __half2 b = __floats2half2_rn(xv.z * r * wv.z, xv.w * r * wv.w);
    ((uint2*)(out + (size_t)row * DD))[t] = make_uint2(h2u(a), h2u(b));
}

// ---------------- f16 tensor-core NT GEMM, 128(M) x 256(N) tiles ----------------
// MODE 0: fp32 C (+R residual).  MODE 2: qkv scatter (q f16 scaled / caches / kt / vt).
// MODE 3: fused silu(gate)*up -> t1 f16 (gate/up interleaved weights).
// BK=32, 6-stage cp.async pipeline.  (frozen: at legacy-HMMA ceiling)
#define HST 40
#define HSTG 6
#define G_AH (128 * HST)
#define G_BH (256 * HST)
#define GEMMH_SMEM (HSTG * (G_AH + G_BH) * 2)   // 184320 B

template <int MODE>
__global__ void __launch_bounds__(512, 1)
gemm_h(const __half* __restrict__ A, const __half* __restrict__ B,
       float* __restrict__ C, const float* __restrict__ R,
       __half* __restrict__ qh, float* __restrict__ kc, float* __restrict__ vc,
       __half* __restrict__ kt, __half* __restrict__ vt, __half* __restrict__ t1,
       int M, int N, int K) {
    extern __shared__ __half smg[];
    uint32_t sA = (uint32_t)__cvta_generic_to_shared(smg);
    uint32_t sB = sA + HSTG * G_AH * 2;

    int tid  = threadIdx.x;
    int warp = tid >> 5, lane = tid & 31;
    int g = lane >> 2, tig = lane & 3;
    int wm = (warp >> 2) * 32;
    int wn = (warp & 3) * 64;
    int bm = blockIdx.y * 128, bn = blockIdx.x * 256;

    int alr = tid >> 2;
    int alk = (tid & 3) * 8;
    const __half* Ag = A + (size_t)(bm + alr) * K + alk;
    uint32_t dA = sA + (uint32_t)(alr * HST + alk) * 2;
    int blr = tid >> 1;
    int blk = (tid & 1) * 16;
    const __half* Bg = B + (size_t)(bn + blr) * K + blk;
    uint32_t dB = sB + (uint32_t)(blr * HST + blk) * 2;

    int aRow = wm + (lane & 15);
    int aColH = (lane >> 4) * 8;
    int bRow = (lane & 7) + ((lane >> 4) & 1) * 8;
    int bColH = ((lane >> 3) & 1) * 8;

    float acc[2][8][4];
#pragma unroll
    for (int i = 0; i < 2; i++)
#pragma unroll
        for (int j = 0; j < 8; j++)
#pragma unroll
            for (int q = 0; q < 4; q++) acc[i][j][q] = 0.f;

#pragma unroll
    for (int s = 0; s < HSTG - 1; s++) {
        uint32_t ao = (uint32_t)(s * G_AH * 2);
        uint32_t bo = (uint32_t)(s * G_BH * 2);
        int ko = s * 32;
        cpa16(dA + ao,      Ag + ko);
        cpa16(dB + bo,      Bg + ko);
        cpa16(dB + bo + 16, Bg + ko + 8);
        cp_commit();
    }

    int rd = 0, wr = HSTG - 1;
    int iters = K >> 5;
    cp_wait<HSTG - 2>();
    __syncthreads();

    for (int it = 0; it < iters; it++) {
        uint32_t stA = sA + (uint32_t)(rd * G_AH * 2);
        uint32_t stB = sB + (uint32_t)(rd * G_BH * 2);
#pragma unroll
        for (int kk = 0; kk < 2; kk++) {
            uint32_t af[2][4], bf[4][4];
#pragma unroll
            for (int mt = 0; mt < 2; mt++)
                ldsm4(af[mt], stA + (uint32_t)((aRow + mt * 16) * HST + kk * 16 + aColH) * 2);
#pragma unroll
            for (int np = 0; np < 4; np++)
                ldsm4(bf[np], stB + (uint32_t)((wn + np * 16 + bRow) * HST + kk * 16 + bColH) * 2);
#pragma unroll
            for (int mt = 0; mt < 2; mt++)
#pragma unroll
                for (int nt = 0; nt < 8; nt++)
                    mma_h(acc[mt][nt], af[mt], &bf[nt >> 1][(nt & 1) * 2]);
        }
        int nk = (it + HSTG - 1) * 32;
        if (nk < K) {
            uint32_t ao = (uint32_t)(wr * G_AH * 2);
            uint32_t bo = (uint32_t)(wr * G_BH * 2);
            cpa16(dA + ao,      Ag + nk);
            cpa16(dB + bo,      Bg + nk);
            cpa16(dB + bo + 16, Bg + nk + 8);
        }
        cp_commit();
        wr = rd;
        rd = (rd + 1 == HSTG) ? 0 : rd + 1;
        cp_wait<HSTG - 2>();
        __syncthreads();
    }

    if (MODE == 0) {
#pragma unroll
        for (int mt = 0; mt < 2; mt++) {
#pragma unroll
            for (int nt = 0; nt < 8; nt++) {
                int r0 = bm + wm + mt * 16 + g;
                int c0 = bn + wn + nt * 8 + 2 * tig;
                size_t o0 = (size_t)r0 * N + c0;
                size_t o1 = (size_t)(r0 + 8) * N + c0;
                float2 v0 = make_float2(acc[mt][nt][0], acc[mt][nt][1]);
                float2 v1 = make_float2(acc[mt][nt][2], acc[mt][nt][3]);
                float2 r4 = *(const float2*)(R + o0);
                v0.x += r4.x; v0.y += r4.y;
                float2 r5 = *(const float2*)(R + o1);
                v1.x += r5.x; v1.y += r5.y;
                *(float2*)(C + o0) = v0;
                *(float2*)(C + o1) = v1;
            }
        }
    } else if (MODE == 2) {
        int kind = bn >> 10;                    // 0=q 1=k 2=v
#pragma unroll
        for (int mt = 0; mt < 2; mt++) {
#pragma unroll
            for (int nt = 0; nt < 8; nt++) {
                int m0 = bm + wm + mt * 16 + g;
                int c0 = bn + wn + nt * 8 + 2 * tig;
                float2 v0 = make_float2(acc[mt][nt][0], acc[mt][nt][1]);
                float2 v1 = make_float2(acc[mt][nt][2], acc[mt][nt][3]);
                if (kind == 0) {
                    *(__half2*)(qh + (size_t)m0 * DD + c0) =
                        __floats2half2_rn(v0.x * 0.125f, v0.y * 0.125f);
                    *(__half2*)(qh + (size_t)(m0 + 8) * DD + c0) =
                        __floats2half2_rn(v1.x * 0.125f, v1.y * 0.125f);
                } else {
                    int cc = c0 & 1023;
                    int hh = cc >> 6, dh = cc & 63;
                    int b0 = m0 >> 11, t0 = m0 & 2047;
                    int bh = b0 * HH + hh;
                    size_t ix0 = ((size_t)bh * TT + t0) * DHH + dh;
                    size_t ix1 = ((size_t)bh * TT + t0 + 8) * DHH + dh;
                    if (kind == 1) {
                        *(float2*)(kc + ix0) = v0;
                        *(float2*)(kc + ix1) = v1;
                        *(__half2*)(kt + ix0) = __floats2half2_rn(v0.x, v0.y);
                        *(__half2*)(kt + ix1) = __floats2half2_rn(v1.x, v1.y);
                    } else {
                        *(float2*)(vc + ix0) = v0;
                        *(float2*)(vc + ix1) = v1;
                        __half* vb0 = vt + (size_t)(bh * DHH + dh) * TT + t0;
                        __half* vb1 = vt + (size_t)(bh * DHH + dh + 1) * TT + t0;
                        vb0[0] = __float2half_rn(v0.x);
                        vb1[0] = __float2half_rn(v0.y);
                        vb0[8] = __float2half_rn(v1.x);
                        vb1[8] = __float2half_rn(v1.y);
                    }
                }
            }
        }
    } else {   // MODE 3: silu fuse; cols [0,128)=gate chunk, [128,256)=up chunk
        __syncthreads();                        // cp.async data consumed; reuse smem
        float* ex = (float*)smg;                // [128][132]
        if (wn >= 128) {
#pragma unroll
            for (int mt = 0; mt < 2; mt++)
#pragma unroll
                for (int nt = 0; nt < 8; nt++) {
                    int lr0 = wm + mt * 16 + g;
                    int cl = wn - 128 + nt * 8 + 2 * tig;
                    *(float2*)(ex + lr0 * 132 + cl) = make_float2(acc[mt][nt][0], acc[mt][nt][1]);
                    *(float2*)(ex + (lr0 + 8) * 132 + cl) = make_float2(acc[mt][nt][2], acc[mt][nt][3]);
                }
        }
        __syncthreads();
        if (wn < 128) {
            int tcol = (bn >> 1);               // output column base = chunk*128
#pragma unroll
            for (int mt = 0; mt < 2; mt++)
#pragma unroll
                for (int nt = 0; nt < 8; nt++) {
                    int lr0 = wm + mt * 16 + g;
                    int cl = wn + nt * 8 + 2 * tig;
                    float2 u0 = *(const float2*)(ex + lr0 * 132 + cl);
                    float2 u1 = *(const float2*)(ex + (lr0 + 8) * 132 + cl);
                    float g0 = acc[mt][nt][0], g1 = acc[mt][nt][1];
                    float g2 = acc[mt][nt][2], g3 = acc[mt][nt][3];
                    g0 = g0 / (1.f + __expf(-g0)) * u0.x;
                    g1 = g1 / (1.f + __expf(-g1)) * u0.y;
                    g2 = g2 / (1.f + __expf(-g2)) * u1.x;
                    g3 = g3 / (1.f + __expf(-g3)) * u1.y;
                    size_t o0 = (size_t)(bm + lr0) * D4 + tcol + cl;
                    size_t o1 = (size_t)(bm + lr0 + 8) * D4 + tcol + cl;
                    *(__half2*)(t1 + o0) = __floats2half2_rn(g0, g1);
                    *(__half2*)(t1 + o1) = __floats2half2_rn(g2, g3);
                }
        }
    }
}

// ---------------- f16 flash attention, balanced 2-item persistent blocks --------
// Work item j (0..511): qt = 15 - (j>>5), bh = j&31 (big-qt first).
// Block i handles items i and 511-i  ->  pair cost (qt+1) sums to 17, uniform.
#define HATR 72
#define HKVF (64 * HATR)
#define ATTH_SMEM ((4 * HKVF + 128 * HATR) * 2)
#define NEGINF __int_as_float(0xff800000)

__global__ void __launch_bounds__(256, 2)
attn_mma(const __half* __restrict__ qh, const __half* __restrict__ kt,
         const __half* __restrict__ vt, __half* __restrict__ out) {
    extern __shared__ __half smh[];
    uint32_t sbase = (uint32_t)__cvta_generic_to_shared(smh);
    const uint32_t sK = sbase;
    const uint32_t sV = sbase + 2 * HKVF * 2;
    const uint32_t sP = sbase + 4 * HKVF * 2;
    __half* pmem = smh + 4 * HKVF;

    int tid = threadIdx.x;
    int warp = tid >> 5, lane = tid & 31;
    int g = lane >> 2, tig = lane & 3;
    int wm = warp * 16;
    int bRow = (lane & 7) + ((lane >> 4) & 1) * 8;
    int bColH = ((lane >> 3) & 1) * 8;
    int aRowP = wm + (lane & 15);
    int aColP = (lane >> 4) * 8;

#pragma unroll 1
    for (int wi = 0; wi < 2; wi++) {
        int j = wi ? (511 - (int)blockIdx.x) : (int)blockIdx.x;
        int qt = 15 - (j >> 5);
        int bh = j & 31;
        int b = bh >> 4, h = bh & 15;
        int q0 = qt * 128;

        const __half* ktb = kt + (size_t)bh * TT * DHH;
        const __half* vtb = vt + (size_t)bh * DHH * TT;

        auto load_tile = [&](int jt, int s) {
            int kv = jt * 64;
            int r = tid >> 2;
            int cbh = (tid & 3) * 16;
            const __half* ksrc = ktb + (size_t)(kv + r) * DHH + cbh;
            const __half* vsrc = vtb + (size_t)r * TT + kv + cbh;
            uint32_t kd = sK + (uint32_t)(s * HKVF + r * HATR + cbh) * 2;
            uint32_t vd = sV + (uint32_t)(s * HKVF + r * HATR + cbh) * 2;
            cpa16(kd,      ksrc);
            cpa16(kd + 16, ksrc + 8);
            cpa16(vd,      vsrc);
            cpa16(vd + 16, vsrc + 8);
        };

        // stage Q (f16, pre-scaled) via cp.async — group 0
        {
            int row = tid >> 1;
            int part = (tid & 1) * 32;
            const __half* src = qh + (size_t)(b * TT + q0 + row) * DD + h * DHH + part;
            uint32_t dst = sP + (uint32_t)(row * HATR + part) * 2;
#pragma unroll
            for (int i = 0; i < 4; i++) cpa16(dst + i * 16, src + i * 8);
            cp_commit();
        }
        load_tile(0, 0);
        cp_commit();

        cp_wait<1>();
        __syncthreads();
        uint32_t qf[4][4];
        {
            int aRow = wm + (lane & 15);
            int aColH = (lane >> 4) * 8;
#pragma unroll
            for (int kk = 0; kk < 4; kk++)
                ldsm4(qf[kk], sP + (uint32_t)(aRow * HATR + kk * 16 + aColH) * 2);
        }
        __syncthreads();

        float o[8][4];
#pragma unroll
        for (int nt = 0; nt < 8; nt++)
#pragma unroll
            for (int i = 0; i < 4; i++) o[nt][i] = 0.f;
        float mx0 = -1e30f, mx1 = -1e30f, l0 = 0.f, l1 = 0.f;

        int nT = 2 * qt + 2;
        for (int jt = 0; jt < nT; jt++) {
            int buf = jt & 1;
            if (jt + 1 < nT) { load_tile(jt + 1, buf ^ 1); cp_commit(); cp_wait<1>(); }
            else             { cp_commit(); cp_wait<0>(); }
            __syncthreads();

            int kv0 = jt * 64;
            if (kv0 <= q0 + wm + 15) {
                float acc[8][4];
#pragma unroll
                for (int nt = 0; nt < 8; nt++)
#pragma unroll
                    for (int i = 0; i < 4; i++) acc[nt][i] = 0.f;
                uint32_t kbase = sK + (uint32_t)(buf * HKVF) * 2;
#pragma unroll
                for (int kk = 0; kk < 4; kk++) {
                    uint32_t bf[4][4];
#pragma unroll
                    for (int np = 0; np < 4; np++)
                        ldsm4(bf[np], kbase + (uint32_t)((np * 16 + bRow) * HATR + kk * 16 + bColH) * 2);
#pragma unroll
                    for (int nt = 0; nt < 8; nt++)
                        mma_h(acc[nt], qf[kk], &bf[nt >> 1][(nt & 1) * 2]);
                }

                int row0 = q0 + wm + g, row1 = row0 + 8;
                if (kv0 + 63 > row0) {
#pragma unroll
                    for (int nt = 0; nt < 8; nt++) {
                        int c = kv0 + nt * 8 + 2 * tig;
                        if (c > row0)     acc[nt][0] = NEGINF;
                        if (c + 1 > row0) acc[nt][1] = NEGINF;
                        if (c > row1)     acc[nt][2] = NEGINF;
                        if (c + 1 > row1) acc[nt][3] = NEGINF;
                    }
                }

                float tm0 = NEGINF, tm1 = NEGINF;
#pragma unroll
                for (int nt = 0; nt < 8; nt++) {
                    tm0 = fmaxf(tm0, fmaxf(acc[nt][0], acc[nt][1]));
                    tm1 = fmaxf(tm1, fmaxf(acc[nt][2], acc[nt][3]));
                }
                tm0 = fmaxf(tm0, __shfl_xor_sync(0xffffffffu, tm0, 1));
                tm0 = fmaxf(tm0, __shfl_xor_sync(0xffffffffu, tm0, 2));
                tm1 = fmaxf(tm1, __shfl_xor_sync(0xffffffffu, tm1, 1));
                tm1 = fmaxf(tm1, __shfl_xor_sync(0xffffffffu, tm1, 2));
                float mn0 = fmaxf(mx0, tm0), mn1 = fmaxf(mx1, tm1);
                float cr0 = __expf(mx0 - mn0), cr1 = __expf(mx1 - mn1);
                mx0 = mn0; mx1 = mn1;
                float rs0 = 0.f, rs1 = 0.f;
                __half2* pr0 = (__half2*)(pmem + (wm + g) * HATR + 2 * tig);
                __half2* pr1 = (__half2*)(pmem + (wm + g + 8) * HATR + 2 * tig);
#pragma unroll
                for (int nt = 0; nt < 8; nt++) {
                    __half2 p0 = __floats2half2_rn(__expf(acc[nt][0] - mn0), __expf(acc[nt][1] - mn0));
                    __half2 p1 = __floats2half2_rn(__expf(acc[nt][2] - mn1), __expf(acc[nt][3] - mn1));
                    pr0[nt * 4] = p0;
                    pr1[nt * 4] = p1;
                    float2 f0 = __half22float2(p0);
                    float2 f1 = __half22float2(p1);
                    rs0 += f0.x + f0.y;
                    rs1 += f1.x + f1.y;
                }
                rs0 += __shfl_xor_sync(0xffffffffu, rs0, 1);
                rs0 += __shfl_xor_sync(0xffffffffu, rs0, 2);
                rs1 += __shfl_xor_sync(0xffffffffu, rs1, 1);
                rs1 += __shfl_xor_sync(0xffffffffu, rs1, 2);
                l0 = l0 * cr0 + rs0;
                l1 = l1 * cr1 + rs1;
#pragma unroll
                for (int nt = 0; nt < 8; nt++) {
                    o[nt][0] *= cr0; o[nt][1] *= cr0;
                    o[nt][2] *= cr1; o[nt][3] *= cr1;
                }
                __syncwarp();

                uint32_t vbase = sV + (uint32_t)(buf * HKVF) * 2;
#pragma unroll
                for (int kk = 0; kk < 4; kk++) {
                    uint32_t pf[4], bv[4][4];
                    ldsm4(pf, sP + (uint32_t)(aRowP * HATR + kk * 16 + aColP) * 2);
#pragma unroll
                    for (int np = 0; np < 4; np++)
                        ldsm4(bv[np], vbase + (uint32_t)((np * 16 + bRow) * HATR + kk * 16 + bColH) * 2);
#pragma unroll
                    for (int nt = 0; nt < 8; nt++)
                        mma_h(o[nt], pf, &bv[nt >> 1][(nt & 1) * 2]);
                }
            }
            __syncthreads();
        }

        float inv0 = 1.f / l0, inv1 = 1.f / l1;
        int r0 = q0 + wm + g;
        __half* o0 = out + (size_t)(b * TT + r0) * DD + h * DHH + 2 * tig;
        __half* o1 = o0 + (size_t)8 * DD;
#pragma unroll
        for (int nt = 0; nt < 8; nt++) {
            *(__half2*)(o0 + nt * 8) = __floats2half2_rn(o[nt][0] * inv0, o[nt][1] * inv0);
            *(__half2*)(o1 + nt * 8) = __floats2half2_rn(o[nt][2] * inv1, o[nt][3] * inv1);
        }
    }
}

// ---------------- launch --------------------------------------------------------
extern "C" void kernel_launch(void* const* d_in, const int* in_sizes, int n_in,
                              void* d_out, int out_size) {
    const float* x       = (const float*)d_in[0];
    const float* w_norm1 = (const float*)d_in[1];
    const float* w_qkv   = (const float*)d_in[2];
    const float* w_proj  = (const float*)d_in[3];
    const float* w_norm2 = (const float*)d_in[4];
    const float* w_gate  = (const float*)d_in[5];
    const float* w_up    = (const float*)d_in[6];
    const float* w_down  = (const float*)d_in[7];

    float* xo = (float*)d_out;
    float* kc = xo + (size_t)MT * DD;
    float* vc = kc + (size_t)BB * HH * TT * DHH;

    __half *h, *qh, *att, *t1, *wh, *ktp, *vtp;
    cudaGetSymbolAddress((void**)&h,   g_h);
    cudaGetSymbolAddress((void**)&qh,  g_qh);
    cudaGetSymbolAddress((void**)&att, g_att);
    cudaGetSymbolAddress((void**)&t1,  g_t1);
    cudaGetSymbolAddress((void**)&wh,  g_wh);
    cudaGetSymbolAddress((void**)&ktp, g_kt);
    cudaGetSymbolAddress((void**)&vtp, g_vt);

    __half* wh_qkv  = wh;
    __half* wh_proj = wh + (size_t)3 * 1024 * 1024;
    __half* wh_gu   = wh + (size_t)4 * 1024 * 1024;
    __half* wh_down = wh + (size_t)12 * 1024 * 1024;

    cudaFuncSetAttribute(gemm_h<0>, cudaFuncAttributeMaxDynamicSharedMemorySize, GEMMH_SMEM);
    cudaFuncSetAttribute(gemm_h<2>, cudaFuncAttributeMaxDynamicSharedMemorySize, GEMMH_SMEM);
    cudaFuncSetAttribute(gemm_h<3>, cudaFuncAttributeMaxDynamicSharedMemorySize, GEMMH_SMEM);
    cudaFuncSetAttribute(attn_mma,  cudaFuncAttributeMaxDynamicSharedMemorySize, ATTH_SMEM);

    // 0. convert all weights (gate/up interleaved)
    cvt_all<<<(16 * 1024 * 1024 / 16) / 256, 256>>>(w_qkv, w_proj, w_gate, w_up, w_down, wh);

    // 1. h = f16(rmsnorm(x) * w1)
    rmsnorm_kernel<<<MT, 256>>>(x, w_norm1, h);
    // 2. qkv GEMM with fused scatter: q->qh (f16, scaled), k/v->caches + kt/vt
    gemm_h<2><<<dim3(D3 / 256, MT / 128), 512, GEMMH_SMEM>>>(
        h, wh_qkv, nullptr, nullptr, qh, kc, vc, ktp, vtp, nullptr, MT, D3, DD);
    // 3. f16 causal flash attention -> att  (256 balanced 2-item blocks)
    attn_mma<<<256, 256, ATTH_SMEM>>>(qh, ktp, vtp, att);
    // 4. x = x + att @ w_proj^T
    gemm_h<0><<<dim3(DD / 256, MT / 128), 512, GEMMH_SMEM>>>(
        att, wh_proj, xo, x, nullptr, nullptr, nullptr, nullptr, nullptr, nullptr, MT, DD, DD);
    // 5. h = f16(rmsnorm(x) * w2)
    rmsnorm_kernel<<<MT, 256>>>(xo, w_norm2, h);
    // 6. gate/up GEMM with fused silu -> t1 (f16)
    gemm_h<3><<<dim3(D8 / 256, MT / 128), 512, GEMMH_SMEM>>>(
        h, wh_gu, nullptr, nullptr, nullptr, nullptr, nullptr, nullptr, nullptr, t1, MT, D8, DD);
    // 7. x += t1 @ w_down^T
    gemm_h<0><<<dim3(DD / 256, MT / 128), 512, GEMMH_SMEM>>>(
        t1, wh_down, xo, xo, nullptr, nullptr, nullptr, nullptr, nullptr, nullptr, MT, DD, D4);
}

// round 13
// speedup vs baseline: 1.2420x; 1.0098x over previous
#include <cuda_runtime.h>
#include <cuda_fp16.h>
#include <math.h>
#include <stdint.h>

#define BB   2
#define TT   2048
#define DD   1024
#define HH   16
#define DHH  64
#define MT   4096            // B*T
#define D3   3072            // 3*D
#define D4   4096            // 4*D
#define D8   8192            // gate+up stacked

// ---------------- scratch (static device arrays; no allocation) ----------------
__device__ __half g_h[MT * DD];                      // rmsnorm output (f16)
__device__ __half g_qh[MT * DD];                     // q, f16, pre-scaled by 1/8
__device__ __half g_att[MT * DD];                    // attention out (f16)
__device__ __half g_t1[(size_t)MT * D4];             // silu(gate)*up (f16)
__device__ __half g_wh[16 * 1024 * 1024];            // converted weights (f16)
__device__ __half g_kt[(size_t)BB * HH * TT * DHH];  // f16 K   [bh][t][dh]
__device__ __half g_vt[(size_t)BB * HH * TT * DHH];  // f16 V^T [bh][dh][t]

// ---------------- helpers -------------------------------------------------------
__device__ __forceinline__ void mma_h(float* c, const uint32_t* a, const uint32_t* b) {
    asm volatile(
        "mma.sync.aligned.m16n8k16.row.col.f32.f16.f16.f32 "
        "{%0,%1,%2,%3}, {%4,%5,%6,%7}, {%8,%9}, {%0,%1,%2,%3};\n"
        : "+f"(c[0]), "+f"(c[1]), "+f"(c[2]), "+f"(c[3])
        : "r"(a[0]), "r"(a[1]), "r"(a[2]), "r"(a[3]), "r"(b[0]), "r"(b[1]));
}
__device__ __forceinline__ void ldsm4(uint32_t* r, uint32_t addr) {
    asm volatile("ldmatrix.sync.aligned.m8n8.x4.shared.b16 {%0,%1,%2,%3}, [%4];"
                 : "=r"(r[0]), "=r"(r[1]), "=r"(r[2]), "=r"(r[3]) : "r"(addr));
}
__device__ __forceinline__ void cpa16(uint32_t dst, const void* src) {
    asm volatile("cp.async.cg.shared.global [%0], [%1], 16;" :: "r"(dst), "l"(src));
}
__device__ __forceinline__ void cp_commit() { asm volatile("cp.async.commit_group;"); }
template <int N>
__device__ __forceinline__ void cp_wait() { asm volatile("cp.async.wait_group %0;" :: "n"(N)); }
__device__ __forceinline__ uint32_t h2u(__half2 h) { return *reinterpret_cast<uint32_t*>(&h); }

// ---------------- fused prologue: rmsnorm1 (blocks < MT) + weight cvt (rest) -----
// cvt dst layout (halves): [0,3M) qkv | [3M,4M) proj | [4M,12M) gate/up INTERLEAVED
// (row chunk c of 256: rows 0-127 = gate[c*128..], 128-255 = up[c*128..]) | [12M,16M) down
__global__ void pre_kernel(const float* __restrict__ x, const float* __restrict__ wn1,
                           __half* __restrict__ hout,
                           const float* __restrict__ wqkv, const float* __restrict__ wproj,
                           const float* __restrict__ wgate, const float* __restrict__ wup,
                           const float* __restrict__ wdown, __half* __restrict__ dst) {
    int t = threadIdx.x;
    if (blockIdx.x < MT) {
        int row = blockIdx.x;
        float4 xv = ((const float4*)(x + (size_t)row * DD))[t];
        float s = xv.x * xv.x + xv.y * xv.y + xv.z * xv.z + xv.w * xv.w;
#pragma unroll
        for (int o = 16; o; o >>= 1) s += __shfl_xor_sync(0xffffffffu, s, o);
        __shared__ float red[8];
        __shared__ float rs;
        if ((t & 31) == 0) red[t >> 5] = s;
        __syncthreads();
        if (t == 0) {
            float tot = 0.f;
#pragma unroll
            for (int i = 0; i < 8; i++) tot += red[i];
            rs = rsqrtf(tot * (1.0f / DD) + 1e-6f);
        }
        __syncthreads();
        float r = rs;
        float4 wv = ((const float4*)wn1)[t];
        __half2 a = __floats2half2_rn(xv.x * r * wv.x, xv.y * r * wv.y);
        __half2 b = __floats2half2_rn(xv.z * r * wv.z, xv.w * r * wv.w);
        ((uint2*)(hout + (size_t)row * DD))[t] = make_uint2(h2u(a), h2u(b));
        return;
    }
    int base_idx = (((int)blockIdx.x - MT) * 256 + t) * 4;
#pragma unroll
    for (int u = 0; u < 4; u++) {
        int idx = base_idx + u;                          // float4 index, 0..4M-1
        float4 v;
        int d;
        if (idx < (3 << 18)) {
            v = ((const float4*)wqkv)[idx];
            d = idx;
        } else if (idx < (4 << 18)) {
            v = ((const float4*)wproj)[idx - (3 << 18)];
            d = idx;
        } else if (idx < (8 << 18)) {
            int i = idx - (4 << 18);
            v = ((const float4*)wgate)[i];
            int j = i >> 8, c4 = i & 255;
            d = (1 << 20) + ((((j >> 7) << 8) + (j & 127)) << 8) + c4;
        } else if (idx < (12 << 18)) {
            int i = idx - (8 << 18);
            v = ((const float4*)wup)[i];
            int j = i >> 8, c4 = i & 255;
            d = (1 << 20) + ((((j >> 7) << 8) + 128 + (j & 127)) << 8) + c4;
        } else {
            v = ((const float4*)wdown)[idx - (12 << 18)];
            d = idx;
        }
        __half2 a = __floats2half2_rn(v.x, v.y);
        __half2 b = __floats2half2_rn(v.z, v.w);
        ((uint2*)dst)[d] = make_uint2(h2u(a), h2u(b));
    }
}

// ---------------- RMSNorm (f16 output) ------------------------------------------
__global__ void rmsnorm_kernel(const float* __restrict__ x,
                               const float* __restrict__ w,
                               __half* __restrict__ out) {
    int row = blockIdx.x;
    int t   = threadIdx.x;
    float4 xv = ((const float4*)(x + (size_t)row * DD))[t];
    float s = xv.x * xv.x + xv.y * xv.y + xv.z * xv.z + xv.w * xv.w;
#pragma unroll
    for (int o = 16; o; o >>= 1) s += __shfl_xor_sync(0xffffffffu, s, o);
    __shared__ float red[8];
    __shared__ float rs;
    if ((t & 31) == 0) red[t >> 5] = s;
    __syncthreads();
    if (t == 0) {
        float tot = 0.f;
#pragma unroll
        for (int i = 0; i < 8; i++) tot += red[i];
        rs = rsqrtf(tot * (1.0f / DD) + 1e-6f);
    }
    __syncthreads();
    float r = rs;
    float4 wv = ((const float4*)w)[t];
    __half2 a = __floats2half2_rn(xv.x * r * wv.x, xv.y * r * wv.y);
    __half2 b = __floats2half2_rn(xv.z * r * wv.z, xv.w * r * wv.w);
    ((uint2*)(out + (size_t)row * DD))[t] = make_uint2(h2u(a), h2u(b));
}

// ---------------- f16 tensor-core NT GEMM, 128(M) x 256(N) tiles ----------------
// MODE 0: fp32 C (+R residual).  MODE 2: qkv scatter.  MODE 3: fused silu.
// BK=32, 6-stage cp.async pipeline.  (frozen: at legacy-HMMA ceiling)
#define HST 40
#define HSTG 6
#define G_AH (128 * HST)
#define G_BH (256 * HST)
#define GEMMH_SMEM (HSTG * (G_AH + G_BH) * 2)   // 184320 B

template <int MODE>
__global__ void __launch_bounds__(512, 1)
gemm_h(const __half* __restrict__ A, const __half* __restrict__ B,
       float* __restrict__ C, const float* __restrict__ R,
       __half* __restrict__ qh, float* __restrict__ kc, float* __restrict__ vc,
       __half* __restrict__ kt, __half* __restrict__ vt, __half* __restrict__ t1,
       int M, int N, int K) {
    extern __shared__ __half smg[];
    uint32_t sA = (uint32_t)__cvta_generic_to_shared(smg);
    uint32_t sB = sA + HSTG * G_AH * 2;

    int tid  = threadIdx.x;
    int warp = tid >> 5, lane = tid & 31;
    int g = lane >> 2, tig = lane & 3;
    int wm = (warp >> 2) * 32;
    int wn = (warp & 3) * 64;
    int bm = blockIdx.y * 128, bn = blockIdx.x * 256;

    int alr = tid >> 2;
    int alk = (tid & 3) * 8;
    const __half* Ag = A + (size_t)(bm + alr) * K + alk;
    uint32_t dA = sA + (uint32_t)(alr * HST + alk) * 2;
    int blr = tid >> 1;
    int blk = (tid & 1) * 16;
    const __half* Bg = B + (size_t)(bn + blr) * K + blk;
    uint32_t dB = sB + (uint32_t)(blr * HST + blk) * 2;

    int aRow = wm + (lane & 15);
    int aColH = (lane >> 4) * 8;
    int bRow = (lane & 7) + ((lane >> 4) & 1) * 8;
    int bColH = ((lane >> 3) & 1) * 8;

    float acc[2][8][4];
#pragma unroll
    for (int i = 0; i < 2; i++)
#pragma unroll
        for (int j = 0; j < 8; j++)
#pragma unroll
            for (int q = 0; q < 4; q++) acc[i][j][q] = 0.f;

#pragma unroll
    for (int s = 0; s < HSTG - 1; s++) {
        uint32_t ao = (uint32_t)(s * G_AH * 2);
        uint32_t bo = (uint32_t)(s * G_BH * 2);
        int ko = s * 32;
        cpa16(dA + ao,      Ag + ko);
        cpa16(dB + bo,      Bg + ko);
        cpa16(dB + bo + 16, Bg + ko + 8);
        cp_commit();
    }

    int rd = 0, wr = HSTG - 1;
    int iters = K >> 5;
    cp_wait<HSTG - 2>();
    __syncthreads();

    for (int it = 0; it < iters; it++) {
        uint32_t stA = sA + (uint32_t)(rd * G_AH * 2);
        uint32_t stB = sB + (uint32_t)(rd * G_BH * 2);
#pragma unroll
        for (int kk = 0; kk < 2; kk++) {
            uint32_t af[2][4], bf[4][4];
#pragma unroll
            for (int mt = 0; mt < 2; mt++)
                ldsm4(af[mt], stA + (uint32_t)((aRow + mt * 16) * HST + kk * 16 + aColH) * 2);
#pragma unroll
            for (int np = 0; np < 4; np++)
                ldsm4(bf[np], stB + (uint32_t)((wn + np * 16 + bRow) * HST + kk * 16 + bColH) * 2);
#pragma unroll
            for (int mt = 0; mt < 2; mt++)
#pragma unroll
                for (int nt = 0; nt < 8; nt++)
                    mma_h(acc[mt][nt], af[mt], &bf[nt >> 1][(nt & 1) * 2]);
        }
        int nk = (it + HSTG - 1) * 32;
        if (nk < K) {
            uint32_t ao = (uint32_t)(wr * G_AH * 2);
            uint32_t bo = (uint32_t)(wr * G_BH * 2);
            cpa16(dA + ao,      Ag + nk);
            cpa16(dB + bo,      Bg + nk);
            cpa16(dB + bo + 16, Bg + nk + 8);
        }
        cp_commit();
        wr = rd;
        rd = (rd + 1 == HSTG) ? 0 : rd + 1;
        cp_wait<HSTG - 2>();
        __syncthreads();
    }

    if (MODE == 0) {
#pragma unroll
        for (int mt = 0; mt < 2; mt++) {
#pragma unroll
            for (int nt = 0; nt < 8; nt++) {
                int r0 = bm + wm + mt * 16 + g;
                int c0 = bn + wn + nt * 8 + 2 * tig;
                size_t o0 = (size_t)r0 * N + c0;
                size_t o1 = (size_t)(r0 + 8) * N + c0;
                float2 v0 = make_float2(acc[mt][nt][0], acc[mt][nt][1]);
                float2 v1 = make_float2(acc[mt][nt][2], acc[mt][nt][3]);
                float2 r4 = *(const float2*)(R + o0);
                v0.x += r4.x; v0.y += r4.y;
                float2 r5 = *(const float2*)(R + o1);
                v1.x += r5.x; v1.y += r5.y;
                *(float2*)(C + o0) = v0;
                *(float2*)(C + o1) = v1;
            }
        }
    } else if (MODE == 2) {
        int kind = bn >> 10;                    // 0=q 1=k 2=v
#pragma unroll
        for (int mt = 0; mt < 2; mt++) {
#pragma unroll
            for (int nt = 0; nt < 8; nt++) {
                int m0 = bm + wm + mt * 16 + g;
                int c0 = bn + wn + nt * 8 + 2 * tig;
                float2 v0 = make_float2(acc[mt][nt][0], acc[mt][nt][1]);
                float2 v1 = make_float2(acc[mt][nt][2], acc[mt][nt][3]);
                if (kind == 0) {
                    *(__half2*)(qh + (size_t)m0 * DD + c0) =
                        __floats2half2_rn(v0.x * 0.125f, v0.y * 0.125f);
                    *(__half2*)(qh + (size_t)(m0 + 8) * DD + c0) =
                        __floats2half2_rn(v1.x * 0.125f, v1.y * 0.125f);
                } else {
                    int cc = c0 & 1023;
                    int hh = cc >> 6, dh = cc & 63;
                    int b0 = m0 >> 11, t0 = m0 & 2047;
                    int bh = b0 * HH + hh;
                    size_t ix0 = ((size_t)bh * TT + t0) * DHH + dh;
                    size_t ix1 = ((size_t)bh * TT + t0 + 8) * DHH + dh;
                    if (kind == 1) {
                        *(float2*)(kc + ix0) = v0;
                        *(float2*)(kc + ix1) = v1;
                        *(__half2*)(kt + ix0) = __floats2half2_rn(v0.x, v0.y);
                        *(__half2*)(kt + ix1) = __floats2half2_rn(v1.x, v1.y);
                    } else {
                        *(float2*)(vc + ix0) = v0;
                        *(float2*)(vc + ix1) = v1;
                        __half* vb0 = vt + (size_t)(bh * DHH + dh) * TT + t0;
                        __half* vb1 = vt + (size_t)(bh * DHH + dh + 1) * TT + t0;
                        vb0[0] = __float2half_rn(v0.x);
                        vb1[0] = __float2half_rn(v0.y);
                        vb0[8] = __float2half_rn(v1.x);
                        vb1[8] = __float2half_rn(v1.y);
                    }
                }
            }
        }
    } else {   // MODE 3: silu fuse; cols [0,128)=gate chunk, [128,256)=up chunk
        __syncthreads();                        // cp.async data consumed; reuse smem
        float* ex = (float*)smg;                // [128][132]
        if (wn >= 128) {
#pragma unroll
            for (int mt = 0; mt < 2; mt++)
#pragma unroll
                for (int nt = 0; nt < 8; nt++) {
                    int lr0 = wm + mt * 16 + g;
                    int cl = wn - 128 + nt * 8 + 2 * tig;
                    *(float2*)(ex + lr0 * 132 + cl) = make_float2(acc[mt][nt][0], acc[mt][nt][1]);
                    *(float2*)(ex + (lr0 + 8) * 132 + cl) = make_float2(acc[mt][nt][2], acc[mt][nt][3]);
                }
        }
        __syncthreads();
        if (wn < 128) {
            int tcol = (bn >> 1);               // output column base = chunk*128
#pragma unroll
            for (int mt = 0; mt < 2; mt++)
#pragma unroll
                for (int nt = 0; nt < 8; nt++) {
                    int lr0 = wm + mt * 16 + g;
                    int cl = wn + nt * 8 + 2 * tig;
                    float2 u0 = *(const float2*)(ex + lr0 * 132 + cl);
                    float2 u1 = *(const float2*)(ex + (lr0 + 8) * 132 + cl);
                    float g0 = acc[mt][nt][0], g1 = acc[mt][nt][1];
                    float g2 = acc[mt][nt][2], g3 = acc[mt][nt][3];
                    g0 = g0 / (1.f + __expf(-g0)) * u0.x;
                    g1 = g1 / (1.f + __expf(-g1)) * u0.y;
                    g2 = g2 / (1.f + __expf(-g2)) * u1.x;
                    g3 = g3 / (1.f + __expf(-g3)) * u1.y;
                    size_t o0 = (size_t)(bm + lr0) * D4 + tcol + cl;
                    size_t o1 = (size_t)(bm + lr0 + 8) * D4 + tcol + cl;
                    *(__half2*)(t1 + o0) = __floats2half2_rn(g0, g1);
                    *(__half2*)(t1 + o1) = __floats2half2_rn(g2, g3);
                }
        }
    }
}

// ---------------- f16 flash attention: balanced pairs + 4-slot KV ring ----------
// Work item j (0..511): qt = 15 - (j>>5), bh = j&31. Block i does items i, 511-i.
// KV tiles processed in pairs; ONE safety barrier + ONE visibility barrier per
// pair (1 barrier/tile vs 2 before). 4-slot ring gives prefetch distance 2-3.
#define HATR 72
#define HKVF (64 * HATR)
#define ATTH_SMEM ((8 * HKVF + 128 * HATR) * 2)   // 92160 B
#define NEGINF __int_as_float(0xff800000)

__global__ void __launch_bounds__(256, 2)
attn_mma(const __half* __restrict__ qh, const __half* __restrict__ kt,
         const __half* __restrict__ vt, __half* __restrict__ out) {
    extern __shared__ __half smh[];
    uint32_t sbase = (uint32_t)__cvta_generic_to_shared(smh);
    const uint32_t sK = sbase;                       // 4 slots
    const uint32_t sV = sbase + 4 * HKVF * 2;        // 4 slots
    const uint32_t sP = sbase + 8 * HKVF * 2;
    __half* pmem = smh + 8 * HKVF;

    int tid = threadIdx.x;
    int warp = tid >> 5, lane = tid & 31;
    int g = lane >> 2, tig = lane & 3;
    int wm = warp * 16;
    int bRow = (lane & 7) + ((lane >> 4) & 1) * 8;
    int bColH = ((lane >> 3) & 1) * 8;
    int aRowP = wm + (lane & 15);
    int aColP = (lane >> 4) * 8;

#pragma unroll 1
    for (int wi = 0; wi < 2; wi++) {
        int j = wi ? (511 - (int)blockIdx.x) : (int)blockIdx.x;
        int qt = 15 - (j >> 5);
        int bh = j & 31;
        int b = bh >> 4, h = bh & 15;
        int q0 = qt * 128;

        const __half* ktb = kt + (size_t)bh * TT * DHH;
        const __half* vtb = vt + (size_t)bh * DHH * TT;

        auto load_tile = [&](int jt, int s) {
            int kv = jt * 64;
            int r = tid >> 2;
            int cbh = (tid & 3) * 16;
            const __half* ksrc = ktb + (size_t)(kv + r) * DHH + cbh;
            const __half* vsrc = vtb + (size_t)r * TT + kv + cbh;
            uint32_t kd = sK + (uint32_t)(s * HKVF + r * HATR + cbh) * 2;
            uint32_t vd = sV + (uint32_t)(s * HKVF + r * HATR + cbh) * 2;
            cpa16(kd,      ksrc);
            cpa16(kd + 16, ksrc + 8);
            cpa16(vd,      vsrc);
            cpa16(vd + 16, vsrc + 8);
        };

        // ---- prologue: Q (group), tile0 (group), tile1 (group)
        {
            int row = tid >> 1;
            int part = (tid & 1) * 32;
            const __half* src = qh + (size_t)(b * TT + q0 + row) * DD + h * DHH + part;
            uint32_t dst = sP + (uint32_t)(row * HATR + part) * 2;
#pragma unroll
            for (int i = 0; i < 4; i++) cpa16(dst + i * 16, src + i * 8);
            cp_commit();
        }
        load_tile(0, 0); cp_commit();
        load_tile(1, 1); cp_commit();

        cp_wait<2>();              // Q arrived
        __syncthreads();
        uint32_t qf[4][4];
        {
            int aRow = wm + (lane & 15);
            int aColH = (lane >> 4) * 8;
#pragma unroll
            for (int kk = 0; kk < 4; kk++)
                ldsm4(qf[kk], sP + (uint32_t)(aRow * HATR + kk * 16 + aColH) * 2);
        }

        float o[8][4];
#pragma unroll
        for (int nt = 0; nt < 8; nt++)
#pragma unroll
            for (int i = 0; i < 4; i++) o[nt][i] = 0.f;
        float mx0 = -1e30f, mx1 = -1e30f, l0 = 0.f, l1 = 0.f;

        int nPairs = qt + 1;       // nT = 2*qt+2 tiles, always even
#pragma unroll 1
        for (int p = 0; p < nPairs; p++) {
            int jt0 = 2 * p;
            __syncthreads();       // safety: slots (jt0+2)&3,(jt0+3)&3 consumed by all
            if (p + 1 < nPairs) {
                load_tile(jt0 + 2, (jt0 + 2) & 3); cp_commit();
                load_tile(jt0 + 3, (jt0 + 3) & 3); cp_commit();
            } else {
                cp_commit(); cp_commit();
            }
            cp_wait<2>();          // tiles jt0, jt0+1 arrived (locally)
            __syncthreads();       // visibility of all threads' copies

#pragma unroll 1
            for (int sub = 0; sub < 2; sub++) {
                int jt = jt0 + sub;
                int kv0 = jt * 64;
                if (kv0 > q0 + wm + 15) continue;   // fully masked for this warp
                int slot = jt & 3;

                float acc[8][4];
#pragma unroll
                for (int nt = 0; nt < 8; nt++)
#pragma unroll
                    for (int i = 0; i < 4; i++) acc[nt][i] = 0.f;
                uint32_t kbase = sK + (uint32_t)(slot * HKVF) * 2;
#pragma unroll
                for (int kk = 0; kk < 4; kk++) {
                    uint32_t bf[4][4];
#pragma unroll
                    for (int np = 0; np < 4; np++)
                        ldsm4(bf[np], kbase + (uint32_t)((np * 16 + bRow) * HATR + kk * 16 + bColH) * 2);
#pragma unroll
                    for (int nt = 0; nt < 8; nt++)
                        mma_h(acc[nt], qf[kk], &bf[nt >> 1][(nt & 1) * 2]);
                }

                int row0 = q0 + wm + g, row1 = row0 + 8;
                if (kv0 + 63 > row0) {
#pragma unroll
                    for (int nt = 0; nt < 8; nt++) {
                        int c = kv0 + nt * 8 + 2 * tig;
                        if (c > row0)     acc[nt][0] = NEGINF;
                        if (c + 1 > row0) acc[nt][1] = NEGINF;
                        if (c > row1)     acc[nt][2] = NEGINF;
                        if (c + 1 > row1) acc[nt][3] = NEGINF;
                    }
                }

                float tm0 = NEGINF, tm1 = NEGINF;
#pragma unroll
                for (int nt = 0; nt < 8; nt++) {
                    tm0 = fmaxf(tm0, fmaxf(acc[nt][0], acc[nt][1]));
                    tm1 = fmaxf(tm1, fmaxf(acc[nt][2], acc[nt][3]));
                }
                tm0 = fmaxf(tm0, __shfl_xor_sync(0xffffffffu, tm0, 1));
                tm0 = fmaxf(tm0, __shfl_xor_sync(0xffffffffu, tm0, 2));
                tm1 = fmaxf(tm1, __shfl_xor_sync(0xffffffffu, tm1, 1));
                tm1 = fmaxf(tm1, __shfl_xor_sync(0xffffffffu, tm1, 2));
                float mn0 = fmaxf(mx0, tm0), mn1 = fmaxf(mx1, tm1);
                float cr0 = __expf(mx0 - mn0), cr1 = __expf(mx1 - mn1);
                mx0 = mn0; mx1 = mn1;
                float rs0 = 0.f, rs1 = 0.f;
                __half2* pr0 = (__half2*)(pmem + (wm + g) * HATR + 2 * tig);
                __half2* pr1 = (__half2*)(pmem + (wm + g + 8) * HATR + 2 * tig);
#pragma unroll
                for (int nt = 0; nt < 8; nt++) {
                    __half2 p0 = __floats2half2_rn(__expf(acc[nt][0] - mn0), __expf(acc[nt][1] - mn0));
                    __half2 p1 = __floats2half2_rn(__expf(acc[nt][2] - mn1), __expf(acc[nt][3] - mn1));
                    pr0[nt * 4] = p0;
                    pr1[nt * 4] = p1;
                    float2 f0 = __half22float2(p0);
                    float2 f1 = __half22float2(p1);
                    rs0 += f0.x + f0.y;
                    rs1 += f1.x + f1.y;
                }
                rs0 += __shfl_xor_sync(0xffffffffu, rs0, 1);
                rs0 += __shfl_xor_sync(0xffffffffu, rs0, 2);
                rs1 += __shfl_xor_sync(0xffffffffu, rs1, 1);
                rs1 += __shfl_xor_sync(0xffffffffu, rs1, 2);
                l0 = l0 * cr0 + rs0;
                l1 = l1 * cr1 + rs1;
#pragma unroll
                for (int nt = 0; nt < 8; nt++) {
                    o[nt][0] *= cr0; o[nt][1] *= cr0;
                    o[nt][2] *= cr1; o[nt][3] *= cr1;
                }
                __syncwarp();      // warp-private P rows visible to own ldsm

                uint32_t vbase = sV + (uint32_t)(slot * HKVF) * 2;
#pragma unroll
                for (int kk = 0; kk < 4; kk++) {
                    uint32_t pf[4], bv[4][4];
                    ldsm4(pf, sP + (uint32_t)(aRowP * HATR + kk * 16 + aColP) * 2);
#pragma unroll
                    for (int np = 0; np < 4; np++)
                        ldsm4(bv[np], vbase + (uint32_t)((np * 16 + bRow) * HATR + kk * 16 + bColH) * 2);
#pragma unroll
                    for (int nt = 0; nt < 8; nt++)
                        mma_h(o[nt], pf, &bv[nt >> 1][(nt & 1) * 2]);
                }
            }
        }

        float inv0 = 1.f / l0, inv1 = 1.f / l1;
        int r0 = q0 + wm + g;
        __half* o0 = out + (size_t)(b * TT + r0) * DD + h * DHH + 2 * tig;
        __half* o1 = o0 + (size_t)8 * DD;
#pragma unroll
        for (int nt = 0; nt < 8; nt++) {
            *(__half2*)(o0 + nt * 8) = __floats2half2_rn(o[nt][0] * inv0, o[nt][1] * inv0);
            *(__half2*)(o1 + nt * 8) = __floats2half2_rn(o[nt][2] * inv1, o[nt][3] * inv1);
        }
        __syncthreads();           // all P/KV reads done before next item restages Q
    }
}

// ---------------- launch --------------------------------------------------------
extern "C" void kernel_launch(void* const* d_in, const int* in_sizes, int n_in,
                              void* d_out, int out_size) {
    const float* x       = (const float*)d_in[0];
    const float* w_norm1 = (const float*)d_in[1];
    const float* w_qkv   = (const float*)d_in[2];
    const float* w_proj  = (const float*)d_in[3];
    const float* w_norm2 = (const float*)d_in[4];
    const float* w_gate  = (const float*)d_in[5];
    const float* w_up    = (const float*)d_in[6];
    const float* w_down  = (const float*)d_in[7];

    float* xo = (float*)d_out;
    float* kc = xo + (size_t)MT * DD;
    float* vc = kc + (size_t)BB * HH * TT * DHH;

    __half *h, *qh, *att, *t1, *wh, *ktp, *vtp;
    cudaGetSymbolAddress((void**)&h,   g_h);
    cudaGetSymbolAddress((void**)&qh,  g_qh);
    cudaGetSymbolAddress((void**)&att, g_att);
    cudaGetSymbolAddress((void**)&t1,  g_t1);
    cudaGetSymbolAddress((void**)&wh,  g_wh);
    cudaGetSymbolAddress((void**)&ktp, g_kt);
    cudaGetSymbolAddress((void**)&vtp, g_vt);

    __half* wh_qkv  = wh;
    __half* wh_proj = wh + (size_t)3 * 1024 * 1024;
    __half* wh_gu   = wh + (size_t)4 * 1024 * 1024;
    __half* wh_down = wh + (size_t)12 * 1024 * 1024;

    cudaFuncSetAttribute(gemm_h<0>, cudaFuncAttributeMaxDynamicSharedMemorySize, GEMMH_SMEM);
    cudaFuncSetAttribute(gemm_h<2>, cudaFuncAttributeMaxDynamicSharedMemorySize, GEMMH_SMEM);
    cudaFuncSetAttribute(gemm_h<3>, cudaFuncAttributeMaxDynamicSharedMemorySize, GEMMH_SMEM);
    cudaFuncSetAttribute(attn_mma,  cudaFuncAttributeMaxDynamicSharedMemorySize, ATTH_SMEM);

    // 0+1. fused: rmsnorm1 (blocks 0..MT-1) + weight cvt (blocks MT..MT+4095)
    pre_kernel<<<MT + 4096, 256>>>(x, w_norm1, h,
                                   w_qkv, w_proj, w_gate, w_up, w_down, wh);
    // 2. qkv GEMM with fused scatter: q->qh (f16, scaled), k/v->caches + kt/vt
    gemm_h<2><<<dim3(D3 / 256, MT / 128), 512, GEMMH_SMEM>>>(
        h, wh_qkv, nullptr, nullptr, qh, kc, vc, ktp, vtp, nullptr, MT, D3, DD);
    // 3. f16 causal flash attention -> att  (256 balanced 2-item blocks)
    attn_mma<<<256, 256, ATTH_SMEM>>>(qh, ktp, vtp, att);
    // 4. x = x + att @ w_proj^T
    gemm_h<0><<<dim3(DD / 256, MT / 128), 512, GEMMH_SMEM>>>(
        att, wh_proj, xo, x, nullptr, nullptr, nullptr, nullptr, nullptr, nullptr, MT, DD, DD);
    // 5. h = f16(rmsnorm(x) * w2)
    rmsnorm_kernel<<<MT, 256>>>(xo, w_norm2, h);
    // 6. gate/up GEMM with fused silu -> t1 (f16)
    gemm_h<3><<<dim3(D8 / 256, MT / 128), 512, GEMMH_SMEM>>>(
        h, wh_gu, nullptr, nullptr, nullptr, nullptr, nullptr, nullptr, nullptr, t1, MT, D8, DD);
    // 7. x += t1 @ w_down^T
    gemm_h<0><<<dim3(DD / 256, MT / 128), 512, GEMMH_SMEM>>>(
        t1, wh_down, xo, xo, nullptr, nullptr, nullptr, nullptr, nullptr, nullptr, MT, DD, D4);
}